// round 1
// baseline (speedup 1.0000x reference)
#include <cuda_runtime.h>

#define NBUS 200000
#define NGEN 50000
#define NN   (NBUS + NGEN)     // 250000 nodes
#define EE0  500000
#define EE1  50000
#define EE2  50000
#define EE   (EE0 + EE1 + EE2) // 600000 edges
#define HDIM 64
#define LAY  3
#define NEG  0.2f

// ---------------- scratch (static device buffers; no allocation) ----------------
__device__ float    g_x [(size_t)NN * HDIM];   // features / message accumulator
__device__ float    g_h [(size_t)NN * HDIM];   // hetero-linear output
__device__ float    g_p [(size_t)NN * HDIM];   // node-side message projection
__device__ float    g_a [NN];                  // h . Watt[:H]   (dst coeff)
__device__ float    g_b [NN];                  // h . Watt[H:2H] (src coeff)
__device__ float    g_s [NN];                  // softmax denominator
__device__ unsigned g_m [NN];                  // softmax max (ordered-uint encoded)
__device__ float    g_ea [(size_t)EE * HDIM];  // edge attr embedding (layer-invariant)
__device__ float    g_eae[(size_t)EE * 16];    // per-layer edge attr emb (16)
__device__ float    g_lg [EE];                 // logits, overwritten by exp values

__device__ __forceinline__ unsigned fenc(float f) {
    unsigned u = __float_as_uint(f);
    return (u & 0x80000000u) ? ~u : (u | 0x80000000u);
}
__device__ __forceinline__ float fdec(unsigned u) {
    return __uint_as_float((u & 0x80000000u) ? (u ^ 0x80000000u) : ~u);
}
__device__ __forceinline__ float lrelu(float v) { return v >= 0.f ? v : NEG * v; }

// ---------------- node input embed: out = relu(xin @ W + b), K in {16,8} ----------------
template <int K>
__global__ void embed_nodes(const float* __restrict__ xin, const float* __restrict__ W,
                            const float* __restrict__ bias, float* __restrict__ xout, int rows) {
    __shared__ float Ws[K * 64];
    __shared__ float bs[64];
    __shared__ float xs[4 * K];
    int tid = threadIdx.x;
    for (int i = tid; i < K * 64; i += 256) Ws[i] = W[i];
    if (tid < 64) bs[tid] = bias[tid];
    int base = blockIdx.x * 4;
    for (int i = tid; i < 4 * K; i += 256) {
        int r = base + i / K;
        xs[i] = (r < rows) ? xin[(size_t)base * K + i] : 0.f;
    }
    __syncthreads();
    int j = tid & 63, s = tid >> 6;
    int n = base + s;
    if (n < rows) {
        float acc = bs[j];
#pragma unroll
        for (int k = 0; k < K; k++) acc += xs[s * K + k] * Ws[k * 64 + j];
        xout[(size_t)n * 64 + j] = fmaxf(acc, 0.f);
    }
}

// ---------------- edge attr embed (K=9, three weight sets by edge range) ----------------
__global__ void embed_edges(const float* __restrict__ ea0, const float* __restrict__ ea1,
                            const float* __restrict__ ea2, const float* __restrict__ W,
                            const float* __restrict__ bias, float* __restrict__ out) {
    __shared__ float Ws[3 * 9 * 64];
    __shared__ float bs[3 * 64];
    __shared__ float xs[4 * 9];
    int tid = threadIdx.x;
    for (int i = tid; i < 3 * 9 * 64; i += 256) Ws[i] = W[i];
    if (tid < 192) bs[tid] = bias[tid];
    int base = blockIdx.x * 4;
    for (int i = tid; i < 36; i += 256) {
        int e = base + i / 9, k = i % 9;
        float v = 0.f;
        if (e < EE) {
            if (e < EE0)            v = ea0[(size_t)e * 9 + k];
            else if (e < EE0 + EE1) v = ea1[(size_t)(e - EE0) * 9 + k];
            else                    v = ea2[(size_t)(e - EE0 - EE1) * 9 + k];
        }
        xs[i] = v;
    }
    __syncthreads();
    int j = tid & 63, s = tid >> 6;
    int e = base + s;
    if (e < EE) {
        int t = e < EE0 ? 0 : (e < EE0 + EE1 ? 1 : 2);
        float acc = bs[t * 64 + j];
#pragma unroll
        for (int k = 0; k < 9; k++) acc += xs[s * 9 + k] * Ws[(t * 9 + k) * 64 + j];
        out[(size_t)e * 64 + j] = fmaxf(acc, 0.f);
    }
}

// ---------------- 64x64 linear: out = (relu_in? relu(in):in) @ W + b ----------------
__global__ void lin64(const float* __restrict__ in, const float* __restrict__ W,
                      const float* __restrict__ bias, float* __restrict__ out,
                      int rows, int relu_in) {
    __shared__ float4 xs[32 * 16];
    int tid = threadIdx.x;
    int j = tid & 63, g = tid >> 6;
    float w[64];
#pragma unroll
    for (int k = 0; k < 64; k++) w[k] = __ldg(&W[k * 64 + j]);
    float bj = __ldg(&bias[j]);
    int base = blockIdx.x * 32;
    int count = min(32, rows - base);
    const float4* in4 = (const float4*)(in + (size_t)base * 64);
    for (int i = tid; i < count * 16; i += 256) {
        float4 v = in4[i];
        if (relu_in) {
            v.x = fmaxf(v.x, 0.f); v.y = fmaxf(v.y, 0.f);
            v.z = fmaxf(v.z, 0.f); v.w = fmaxf(v.w, 0.f);
        }
        xs[i] = v;
    }
    __syncthreads();
    for (int n = g; n < count; n += 4) {
        float acc = bj;
#pragma unroll
        for (int kk = 0; kk < 16; kk++) {
            float4 v = xs[n * 16 + kk];
            acc += v.x * w[4 * kk] + v.y * w[4 * kk + 1] + v.z * w[4 * kk + 2] + v.w * w[4 * kk + 3];
        }
        out[(size_t)(base + n) * 64 + j] = acc;
    }
}

// ---------------- per-node attention scalars a = h.wa, b = h.wb (warp/node) ----------------
__global__ void ab_kernel(const float* __restrict__ h, const float* __restrict__ watt,
                          float* __restrict__ a, float* __restrict__ b) {
    int gt = blockIdx.x * 256 + threadIdx.x;
    int n = gt >> 5, lane = gt & 31;
    if (n >= NN) return;
    float v0 = h[(size_t)n * 64 + lane];
    float v1 = h[(size_t)n * 64 + 32 + lane];
    float pa = v0 * __ldg(&watt[lane])      + v1 * __ldg(&watt[32 + lane]);
    float pb = v0 * __ldg(&watt[64 + lane]) + v1 * __ldg(&watt[96 + lane]);
#pragma unroll
    for (int off = 16; off; off >>= 1) {
        pa += __shfl_down_sync(0xffffffffu, pa, off);
        pb += __shfl_down_sync(0xffffffffu, pb, off);
    }
    if (lane == 0) { a[n] = pa; b[n] = pb; }
}

// ---------------- zero accumulator + softmax state ----------------
__global__ void zero_kernel(float* __restrict__ x, float* __restrict__ s, unsigned* __restrict__ m) {
    int i = blockIdx.x * 256 + threadIdx.x;
    if (i < NN * 64) { x[i] = 0.f; return; }
    int r = i - NN * 64;
    if (r < NN) { s[r] = 0.f; return; }
    r -= NN;
    if (r < NN) m[r] = 0u;
}

// ---------------- eae = leaky(ea @ Wea), logits (16 edges/block) ----------------
__global__ void eae_logit_kernel(const float* __restrict__ ea, const float* __restrict__ Wea,
                                 const float* __restrict__ Et, const float* __restrict__ watt,
                                 const float* __restrict__ a, const float* __restrict__ b,
                                 const int* __restrict__ src, const int* __restrict__ dst,
                                 const int* __restrict__ etype,
                                 float* __restrict__ eae, float* __restrict__ logit) {
    __shared__ float Ws[64 * 16];
    __shared__ float w4[16];
    __shared__ float c[3];
    __shared__ float eas[16 * 64];
    int tid = threadIdx.x;
    for (int i = tid; i < 1024; i += 256) Ws[i] = Wea[i];
    if (tid < 16) w4[tid] = watt[144 + tid];
    if (tid >= 32 && tid < 35) {
        int t = tid - 32;
        float acc = 0.f;
        for (int jj = 0; jj < 16; jj++) acc += lrelu(Et[t * 16 + jj]) * watt[128 + jj];
        c[t] = acc;
    }
    int base = blockIdx.x * 16;
    int cnt = min(16, EE - base);
    for (int i = tid; i < cnt * 64; i += 256) eas[i] = ea[(size_t)base * 64 + i];
    __syncthreads();
    int j = tid & 15, s = tid >> 4;
    float acc = 0.f;
    if (s < cnt) {
#pragma unroll
        for (int k = 0; k < 64; k++) acc += eas[s * 64 + k] * Ws[k * 16 + j];
        acc = lrelu(acc);
        eae[(size_t)(base + s) * 16 + j] = acc;
    }
    float d = (s < cnt) ? acc * w4[j] : 0.f;
#pragma unroll
    for (int off = 8; off; off >>= 1) d += __shfl_down_sync(0xffffffffu, d, off, 16);
    if (j == 0 && s < cnt) {
        int e = base + s;
        float lg = a[dst[e]] + b[src[e]] + c[etype[e]] + d;
        logit[e] = lrelu(lg);
    }
}

// ---------------- segment max (atomicMax, ordered-uint) ----------------
__global__ void max_kernel(const float* __restrict__ logit, const int* __restrict__ dst,
                           unsigned* __restrict__ m) {
    int e = blockIdx.x * 256 + threadIdx.x;
    if (e < EE) atomicMax(&m[dst[e]], fenc(logit[e]));
}

// ---------------- exp + segment sum (in-place logit -> ex) ----------------
__global__ void exp_kernel(float* __restrict__ logit, const int* __restrict__ dst,
                           const unsigned* __restrict__ m, float* __restrict__ s) {
    int e = blockIdx.x * 256 + threadIdx.x;
    if (e >= EE) return;
    int de = dst[e];
    float f = expf(logit[e] - fdec(m[de]));
    logit[e] = f;
    atomicAdd(&s[de], f);
}

// ---------------- message + scatter: accum[dst] += alpha*(p[src] + eae@Wl2) ----------------
__global__ void msg_kernel(const float* __restrict__ p, const float* __restrict__ eae,
                           const float* __restrict__ Wl2, const float* __restrict__ ex,
                           const float* __restrict__ ssum, const int* __restrict__ src,
                           const int* __restrict__ dst, float* __restrict__ accum) {
    __shared__ float Ws[16 * 64];
    __shared__ float eaes[4 * 16];
    int tid = threadIdx.x;
    for (int i = tid; i < 1024; i += 256) Ws[i] = Wl2[i];
    int base = blockIdx.x * 4;
    if (tid < 64) {
        int e = base + tid / 16;
        eaes[tid] = (e < EE) ? eae[(size_t)e * 16 + (tid & 15)] : 0.f;
    }
    __syncthreads();
    int j = tid & 63, s = tid >> 6;
    int e = base + s;
    if (e >= EE) return;
    int de = dst[e], se = src[e];
    float alpha = ex[e] / (ssum[de] + 1e-16f);
    float acc = p[(size_t)se * 64 + j];
#pragma unroll
    for (int k = 0; k < 16; k++) acc += eaes[s * 16 + k] * Ws[k * 64 + j];
    atomicAdd(&accum[(size_t)de * 64 + j], alpha * acc);
}

// ---------------- output: sigmoid(relu(x) @ W_out + b) (warp/node) ----------------
__global__ void out_kernel(const float* __restrict__ x, const float* __restrict__ Wb,
                           const float* __restrict__ bb, const float* __restrict__ Wg,
                           const float* __restrict__ bg, float* __restrict__ out) {
    int gt = blockIdx.x * 256 + threadIdx.x;
    int n = gt >> 5, lane = gt & 31;
    if (n >= NN) return;
    float v0 = fmaxf(x[(size_t)n * 64 + lane], 0.f);
    float v1 = fmaxf(x[(size_t)n * 64 + 32 + lane], 0.f);
    const float* W = (n < NBUS) ? Wb : Wg;
    float a0 = v0 * __ldg(&W[lane * 2])     + v1 * __ldg(&W[(lane + 32) * 2]);
    float a1 = v0 * __ldg(&W[lane * 2 + 1]) + v1 * __ldg(&W[(lane + 32) * 2 + 1]);
#pragma unroll
    for (int off = 16; off; off >>= 1) {
        a0 += __shfl_down_sync(0xffffffffu, a0, off);
        a1 += __shfl_down_sync(0xffffffffu, a1, off);
    }
    if (lane == 0) {
        const float* bias = (n < NBUS) ? bb : bg;
        float z0 = a0 + bias[0], z1 = a1 + bias[1];
        out[(size_t)n * 2 + 0] = 1.f / (1.f + expf(-z0));
        out[(size_t)n * 2 + 1] = 1.f / (1.f + expf(-z1));
    }
}

// ---------------- host launcher ----------------
extern "C" void kernel_launch(void* const* d_in, const int* in_sizes, int n_in,
                              void* d_out, int out_size) {
    const float* x_bus     = (const float*)d_in[0];
    const float* x_gen     = (const float*)d_in[1];
    const float* ea0       = (const float*)d_in[2];
    const float* ea1       = (const float*)d_in[3];
    const float* ea2       = (const float*)d_in[4];
    const float* W_lin_bus = (const float*)d_in[5];
    const float* b_lin_bus = (const float*)d_in[6];
    const float* W_lin_gen = (const float*)d_in[7];
    const float* b_lin_gen = (const float*)d_in[8];
    const float* W_elin    = (const float*)d_in[9];
    const float* b_elin    = (const float*)d_in[10];
    const float* Wn        = (const float*)d_in[11];
    const float* bn        = (const float*)d_in[12];
    const float* Et        = (const float*)d_in[13];
    const float* Wea       = (const float*)d_in[14];
    const float* Watt      = (const float*)d_in[15];
    const float* Wl        = (const float*)d_in[16];
    const float* bl        = (const float*)d_in[17];
    const float* W_out_bus = (const float*)d_in[18];
    const float* b_out_bus = (const float*)d_in[19];
    const float* W_out_gen = (const float*)d_in[20];
    const float* b_out_gen = (const float*)d_in[21];
    const int*   src       = (const int*)d_in[22];
    const int*   dst       = (const int*)d_in[23];
    const int*   etype     = (const int*)d_in[24];
    float* out = (float*)d_out;

    float *x, *h, *p, *a, *b, *s, *ea, *eae, *lg;
    unsigned* m;
    cudaGetSymbolAddress((void**)&x,   g_x);
    cudaGetSymbolAddress((void**)&h,   g_h);
    cudaGetSymbolAddress((void**)&p,   g_p);
    cudaGetSymbolAddress((void**)&a,   g_a);
    cudaGetSymbolAddress((void**)&b,   g_b);
    cudaGetSymbolAddress((void**)&s,   g_s);
    cudaGetSymbolAddress((void**)&m,   g_m);
    cudaGetSymbolAddress((void**)&ea,  g_ea);
    cudaGetSymbolAddress((void**)&eae, g_eae);
    cudaGetSymbolAddress((void**)&lg,  g_lg);

    // input embeds
    embed_nodes<16><<<(NBUS + 3) / 4, 256>>>(x_bus, W_lin_bus, b_lin_bus, x, NBUS);
    embed_nodes<8> <<<(NGEN + 3) / 4, 256>>>(x_gen, W_lin_gen, b_lin_gen, x + (size_t)NBUS * 64, NGEN);
    embed_edges    <<<(EE + 3) / 4,   256>>>(ea0, ea1, ea2, W_elin, b_elin, ea);

    for (int l = 0; l < LAY; l++) {
        const float* Wn0  = Wn + (size_t)(l * 2) * 4096;
        const float* Wn1  = Wn + (size_t)(l * 2 + 1) * 4096;
        const float* bn0  = bn + (l * 2) * 64;
        const float* bn1  = bn + (l * 2 + 1) * 64;
        const float* Wl1  = Wl + (size_t)l * 80 * 64;
        const float* Wl2  = Wl1 + 64 * 64;
        const float* bll  = bl + l * 64;
        const float* wat  = Watt + l * 160;
        const float* Etl  = Et + l * 48;
        const float* Weal = Wea + (size_t)l * 1024;

        // h = heterolinear(relu(x))  (relu idempotent on layer 0)
        lin64<<<(NBUS + 31) / 32, 256>>>(x, Wn0, bn0, h, NBUS, 1);
        lin64<<<(NGEN + 31) / 32, 256>>>(x + (size_t)NBUS * 64, Wn1, bn1, h + (size_t)NBUS * 64, NGEN, 1);
        // p = h @ Wl1 + bl
        lin64<<<(NN + 31) / 32, 256>>>(h, Wl1, bll, p, NN, 0);
        // a,b per-node attention scalars
        ab_kernel<<<(NN * 32 + 255) / 256, 256>>>(h, wat, a, b);
        // reset accumulator + softmax state (x already consumed by lin64 above)
        zero_kernel<<<(NN * 66 + 255) / 256, 256>>>(x, s, m);
        // per-edge: eae + logits
        eae_logit_kernel<<<(EE + 15) / 16, 256>>>(ea, Weal, Etl, wat, a, b, src, dst, etype, eae, lg);
        // segment softmax
        max_kernel<<<(EE + 255) / 256, 256>>>(lg, dst, m);
        exp_kernel<<<(EE + 255) / 256, 256>>>(lg, dst, m, s);
        // weighted message scatter into x
        msg_kernel<<<(EE + 3) / 4, 256>>>(p, eae, Wl2, lg, s, src, dst, x);
    }

    out_kernel<<<(NN * 32 + 255) / 256, 256>>>(x, W_out_bus, b_out_bus, W_out_gen, b_out_gen, out);
}

// round 2
// speedup vs baseline: 1.8712x; 1.8712x over previous
#include <cuda_runtime.h>

#define NBUS 200000
#define NGEN 50000
#define NN   (NBUS + NGEN)
#define EE0  500000
#define EE1  50000
#define EE2  50000
#define EE   (EE0 + EE1 + EE2)
#define LAY  3
#define NEG  0.2f

// ---------------- static device scratch ----------------
__device__ __align__(16) float g_Wc[6][4096];   // folded node weight [l*2+t][k][j]
__device__ float g_bc[6][64];                   // folded node bias
__device__ float g_va[6][64];                   // folded attention vec (dst)
__device__ float g_vb[6][64];                   // folded attention vec (src)
__device__ float g_cab[6][2];                   // folded attention scalars
__device__ float g_c3[9];                       // edge-type logit constants [l][etype]
__device__ __align__(16) float g_x[(size_t)NN * 64];
__device__ __align__(16) float g_p[(size_t)NN * 64];
__device__ float    g_a[NN];
__device__ float    g_b[NN];
__device__ float    g_s[NN];
__device__ unsigned g_m[NN];
__device__ __align__(16) float g_eae[(size_t)LAY * EE * 16];
__device__ float g_d [(size_t)LAY * EE];
__device__ float g_lg[EE];

__device__ __forceinline__ unsigned fenc(float f) {
    unsigned u = __float_as_uint(f);
    return (u & 0x80000000u) ? ~u : (u | 0x80000000u);
}
__device__ __forceinline__ float fdec(unsigned u) {
    return __uint_as_float((u & 0x80000000u) ? (u ^ 0x80000000u) : ~u);
}
__device__ __forceinline__ float lrelu(float v) { return v >= 0.f ? v : NEG * v; }

// ---------------- weight folding (once per call, 6 blocks) ----------------
__global__ void prep_weights(const float* __restrict__ Wn, const float* __restrict__ bn,
                             const float* __restrict__ Wl, const float* __restrict__ bl,
                             const float* __restrict__ Watt, const float* __restrict__ Et) {
    int blk = blockIdx.x;             // l*2 + t
    int l = blk >> 1, t = blk & 1;
    __shared__ float WnS[4096], Wl1S[4096];
    const float* wn   = Wn + (size_t)blk * 4096;
    const float* wl1  = Wl + (size_t)l * 80 * 64;      // first 64 rows of Wl[l]
    const float* watt = Watt + l * 160;
    const float* bnl  = bn + blk * 64;
    int tid = threadIdx.x;
    for (int i = tid; i < 4096; i += 256) { WnS[i] = wn[i]; Wl1S[i] = wl1[i]; }
    __syncthreads();
    for (int idx = tid; idx < 4096; idx += 256) {
        int k = idx >> 6, j = idx & 63;
        float s = 0.f;
#pragma unroll 8
        for (int m = 0; m < 64; m++) s += WnS[k * 64 + m] * Wl1S[m * 64 + j];
        g_Wc[blk][idx] = s;
    }
    if (tid < 64) {
        int j = tid;
        float s = bl[l * 64 + j];
        for (int m = 0; m < 64; m++) s += bnl[m] * Wl1S[m * 64 + j];
        g_bc[blk][j] = s;
        float sa = 0.f, sb = 0.f;
        for (int m = 0; m < 64; m++) {
            sa += WnS[j * 64 + m] * watt[m];
            sb += WnS[j * 64 + m] * watt[64 + m];
        }
        g_va[blk][j] = sa; g_vb[blk][j] = sb;
    } else if (tid == 64) {
        float ca = 0.f, cb = 0.f;
        for (int m = 0; m < 64; m++) { ca += bnl[m] * watt[m]; cb += bnl[m] * watt[64 + m]; }
        g_cab[blk][0] = ca; g_cab[blk][1] = cb;
    } else if (tid >= 128 && tid < 131 && t == 0) {
        int tt = tid - 128;
        float s = 0.f;
        for (int j = 0; j < 16; j++) s += lrelu(Et[l * 48 + tt * 16 + j]) * watt[128 + j];
        g_c3[l * 3 + tt] = s;
    }
}

// ---------------- node input embed: out = relu(xin @ W + b) ----------------
template <int K>
__global__ void embed_nodes(const float* __restrict__ xin, const float* __restrict__ W,
                            const float* __restrict__ bias, float* __restrict__ xout, int rows) {
    __shared__ float Ws[K * 64];
    __shared__ float bs[64];
    __shared__ float xs[4 * K];
    int tid = threadIdx.x;
    for (int i = tid; i < K * 64; i += 256) Ws[i] = W[i];
    if (tid < 64) bs[tid] = bias[tid];
    int base = blockIdx.x * 4;
    for (int i = tid; i < 4 * K; i += 256) {
        int r = base + i / K;
        xs[i] = (r < rows) ? xin[(size_t)base * K + i] : 0.f;
    }
    __syncthreads();
    int j = tid & 63, s = tid >> 6;
    int n = base + s;
    if (n < rows) {
        float acc = bs[j];
#pragma unroll
        for (int k = 0; k < K; k++) acc += xs[s * K + k] * Ws[k * 64 + j];
        xout[(size_t)n * 64 + j] = fmaxf(acc, 0.f);
    }
}

// ---------------- edge precompute: eae[l], d[l] for all 3 layers (once) ----------------
#define EPB 32
__global__ void edge_pre(const float* __restrict__ ea0, const float* __restrict__ ea1,
                         const float* __restrict__ ea2, const float* __restrict__ W_elin,
                         const float* __restrict__ b_elin, const float* __restrict__ Wea,
                         const float* __restrict__ Watt) {
    __shared__ float We[1728], be[192], WeaS[3072], w4s[48];
    __shared__ float raw[EPB * 9];
    __shared__ float ea64[EPB][64];
    int tid = threadIdx.x;
    for (int i = tid; i < 1728; i += 256) We[i] = W_elin[i];
    if (tid < 192) be[tid] = b_elin[tid];
    for (int i = tid; i < 3072; i += 256) WeaS[i] = Wea[i];
    if (tid < 48) w4s[tid] = Watt[(tid >> 4) * 160 + 144 + (tid & 15)];
    int base = blockIdx.x * EPB;
    for (int i = tid; i < EPB * 9; i += 256) {
        int e = base + i / 9, k = i % 9;
        float v = 0.f;
        if (e < EE) {
            if (e < EE0)            v = ea0[(size_t)e * 9 + k];
            else if (e < EE0 + EE1) v = ea1[(size_t)(e - EE0) * 9 + k];
            else                    v = ea2[(size_t)(e - EE0 - EE1) * 9 + k];
        }
        raw[i] = v;
    }
    __syncthreads();
    // phase 1: ea64 = relu(raw @ W_elin[type] + b)
    for (int idx = tid; idx < EPB * 64; idx += 256) {
        int s = idx >> 6, j = idx & 63;
        int e = base + s;
        int t = (e < EE0) ? 0 : ((e < EE0 + EE1) ? 1 : 2);
        float acc = be[t * 64 + j];
#pragma unroll
        for (int k = 0; k < 9; k++) acc += raw[s * 9 + k] * We[(t * 9 + k) * 64 + j];
        ea64[s][j] = fmaxf(acc, 0.f);
    }
    __syncthreads();
    // phase 2: per layer eae16 = leaky(ea64 @ Wea[l]), d = eae16 . w4
    int j = tid & 15;
#pragma unroll
    for (int l = 0; l < 3; l++) {
#pragma unroll
        for (int half = 0; half < 2; half++) {
            int s = (tid >> 4) + half * 16;
            int e = base + s;
            float acc = 0.f;
#pragma unroll 8
            for (int m = 0; m < 64; m++) acc += ea64[s][m] * WeaS[l * 1024 + m * 16 + j];
            acc = lrelu(acc);
            float dd = acc * w4s[l * 16 + j];
#pragma unroll
            for (int off = 8; off; off >>= 1) dd += __shfl_down_sync(0xffffffffu, dd, off, 16);
            if (e < EE) {
                g_eae[(size_t)l * EE * 16 + (size_t)e * 16 + j] = acc;
                if (j == 0) g_d[(size_t)l * EE + e] = dd;
            }
        }
    }
}

// ---------------- fused node GEMM: p = relu(x)@Wc + bc, a/b = relu(x).va/vb + c ----------------
__global__ void gemm_node(const float* __restrict__ x, const float* __restrict__ Wc,
                          const float* __restrict__ bc, const float* __restrict__ va,
                          const float* __restrict__ vb, const float* __restrict__ cab,
                          float* __restrict__ p, float* __restrict__ a, float* __restrict__ b,
                          int rows) {
    __shared__ float Ws[4096];            // [k][j]
    __shared__ float xsT[64 * 68];        // [k][row], pad 68 for banks + float4 align
    __shared__ float vas[64], vbs[64], bcs[64];
    int tid = threadIdx.x;
    for (int i = tid; i < 4096; i += 256) Ws[i] = Wc[i];
    if (tid < 64) { vas[tid] = va[tid]; vbs[tid] = vb[tid]; bcs[tid] = bc[tid]; }
    int base = blockIdx.x * 64;
    int cnt = min(64, rows - base);
    for (int idx = tid; idx < 4096; idx += 256) {
        int r = idx >> 6, k = idx & 63;
        float v = (r < cnt) ? fmaxf(x[(size_t)(base + r) * 64 + k], 0.f) : 0.f;
        xsT[k * 68 + r] = v;
    }
    __syncthreads();
    int ty = tid >> 4, tx = tid & 15;
    float4 acc0, acc1, acc2, acc3;
    {
        float4 bc4 = ((const float4*)bcs)[tx];
        acc0 = bc4; acc1 = bc4; acc2 = bc4; acc3 = bc4;
    }
#pragma unroll 8
    for (int k = 0; k < 64; k++) {
        float4 av = *(const float4*)&xsT[k * 68 + 4 * ty];
        float4 wv = ((const float4*)Ws)[k * 16 + tx];
        acc0.x += av.x * wv.x; acc0.y += av.x * wv.y; acc0.z += av.x * wv.z; acc0.w += av.x * wv.w;
        acc1.x += av.y * wv.x; acc1.y += av.y * wv.y; acc1.z += av.y * wv.z; acc1.w += av.y * wv.w;
        acc2.x += av.z * wv.x; acc2.y += av.z * wv.y; acc2.z += av.z * wv.z; acc2.w += av.z * wv.w;
        acc3.x += av.w * wv.x; acc3.y += av.w * wv.y; acc3.z += av.w * wv.z; acc3.w += av.w * wv.w;
    }
    float4* p4 = (float4*)p;
    int r0 = 4 * ty;
    if (r0 + 0 < cnt) p4[(size_t)(base + r0 + 0) * 16 + tx] = acc0;
    if (r0 + 1 < cnt) p4[(size_t)(base + r0 + 1) * 16 + tx] = acc1;
    if (r0 + 2 < cnt) p4[(size_t)(base + r0 + 2) * 16 + tx] = acc2;
    if (r0 + 3 < cnt) p4[(size_t)(base + r0 + 3) * 16 + tx] = acc3;
    // a,b: 4 threads per row
    int row = tid >> 2, q = tid & 3;
    float pa = 0.f, pb = 0.f;
#pragma unroll
    for (int kk = 0; kk < 16; kk++) {
        int k = q * 16 + kk;
        float v = xsT[k * 68 + row];
        pa += v * vas[k]; pb += v * vbs[k];
    }
#pragma unroll
    for (int off = 2; off; off >>= 1) {
        pa += __shfl_down_sync(0xffffffffu, pa, off, 4);
        pb += __shfl_down_sync(0xffffffffu, pb, off, 4);
    }
    if (q == 0 && row < cnt) {
        a[base + row] = pa + cab[0];
        b[base + row] = pb + cab[1];
    }
}

// ---------------- zero accumulator + softmax state ----------------
__global__ void zero_kernel(float4* __restrict__ x4, float* __restrict__ s, unsigned* __restrict__ m) {
    int i = blockIdx.x * 256 + threadIdx.x;
    if (i < NN * 16) { x4[i] = make_float4(0.f, 0.f, 0.f, 0.f); return; }
    int r = i - NN * 16;
    if (r < NN) { s[r] = 0.f; return; }
    r -= NN;
    if (r < NN) m[r] = 0u;
}

// ---------------- logits + fused segment max ----------------
__global__ void logit_kernel(const float* __restrict__ a, const float* __restrict__ b,
                             const float* __restrict__ d, const float* __restrict__ c3,
                             const int* __restrict__ src, const int* __restrict__ dst,
                             const int* __restrict__ etype,
                             float* __restrict__ lg, unsigned* __restrict__ m) {
    int e = blockIdx.x * 256 + threadIdx.x;
    if (e >= EE) return;
    int de = dst[e];
    float v = lrelu(a[de] + b[src[e]] + c3[etype[e]] + d[e]);
    lg[e] = v;
    atomicMax(&m[de], fenc(v));
}

// ---------------- exp + segment sum ----------------
__global__ void exp_kernel(float* __restrict__ lg, const int* __restrict__ dst,
                           const unsigned* __restrict__ m, float* __restrict__ s) {
    int e = blockIdx.x * 256 + threadIdx.x;
    if (e >= EE) return;
    int de = dst[e];
    float f = expf(lg[e] - fdec(m[de]));
    lg[e] = f;
    atomicAdd(&s[de], f);
}

// ---------------- message + vectorized scatter ----------------
#define MEPB 64
__global__ void msg_kernel(const float* __restrict__ p, const float* __restrict__ eae,
                           const float* __restrict__ Wl2, const float* __restrict__ ex,
                           const float* __restrict__ ssum, const int* __restrict__ src,
                           const int* __restrict__ dst, float* __restrict__ accum) {
    __shared__ float Wl2S[1024];          // [k][j] 16x64
    __shared__ float eaes[16][16];
    int tid = threadIdx.x;
    for (int i = tid; i < 1024; i += 256) Wl2S[i] = Wl2[i];
    int s = tid >> 4, t = tid & 15;
#pragma unroll
    for (int pass = 0; pass < MEPB / 16; pass++) {
        int base = blockIdx.x * MEPB + pass * 16;
        __syncthreads();
        {
            int e = base + (tid >> 4);
            eaes[tid >> 4][tid & 15] = (e < EE) ? eae[(size_t)e * 16 + (tid & 15)] : 0.f;
        }
        __syncthreads();
        int e = base + s;
        if (e < EE) {
            int de = dst[e], se = src[e];
            float alpha = ex[e] / (ssum[de] + 1e-16f);
            float4 acc = ((const float4*)p)[(size_t)se * 16 + t];
#pragma unroll
            for (int k = 0; k < 16; k++) {
                float ev = eaes[s][k];
                float4 wv = ((const float4*)Wl2S)[k * 16 + t];
                acc.x += ev * wv.x; acc.y += ev * wv.y; acc.z += ev * wv.z; acc.w += ev * wv.w;
            }
            acc.x *= alpha; acc.y *= alpha; acc.z *= alpha; acc.w *= alpha;
            float* addr = accum + (size_t)de * 64 + 4 * t;
            asm volatile("red.global.add.v4.f32 [%0], {%1, %2, %3, %4};"
                         :: "l"(addr), "f"(acc.x), "f"(acc.y), "f"(acc.z), "f"(acc.w)
                         : "memory");
        }
    }
}

// ---------------- output: sigmoid(relu(x) @ W_out + b) ----------------
__global__ void out_kernel(const float* __restrict__ x, const float* __restrict__ Wb,
                           const float* __restrict__ bb, const float* __restrict__ Wg,
                           const float* __restrict__ bg, float* __restrict__ out) {
    int gt = blockIdx.x * 256 + threadIdx.x;
    int n = gt >> 5, lane = gt & 31;
    if (n >= NN) return;
    float v0 = fmaxf(x[(size_t)n * 64 + lane], 0.f);
    float v1 = fmaxf(x[(size_t)n * 64 + 32 + lane], 0.f);
    const float* W = (n < NBUS) ? Wb : Wg;
    float a0 = v0 * __ldg(&W[lane * 2])     + v1 * __ldg(&W[(lane + 32) * 2]);
    float a1 = v0 * __ldg(&W[lane * 2 + 1]) + v1 * __ldg(&W[(lane + 32) * 2 + 1]);
#pragma unroll
    for (int off = 16; off; off >>= 1) {
        a0 += __shfl_down_sync(0xffffffffu, a0, off);
        a1 += __shfl_down_sync(0xffffffffu, a1, off);
    }
    if (lane == 0) {
        const float* bias = (n < NBUS) ? bb : bg;
        float z0 = a0 + bias[0], z1 = a1 + bias[1];
        out[(size_t)n * 2 + 0] = 1.f / (1.f + expf(-z0));
        out[(size_t)n * 2 + 1] = 1.f / (1.f + expf(-z1));
    }
}

// ---------------- host launcher ----------------
extern "C" void kernel_launch(void* const* d_in, const int* in_sizes, int n_in,
                              void* d_out, int out_size) {
    const float* x_bus     = (const float*)d_in[0];
    const float* x_gen     = (const float*)d_in[1];
    const float* ea0       = (const float*)d_in[2];
    const float* ea1       = (const float*)d_in[3];
    const float* ea2       = (const float*)d_in[4];
    const float* W_lin_bus = (const float*)d_in[5];
    const float* b_lin_bus = (const float*)d_in[6];
    const float* W_lin_gen = (const float*)d_in[7];
    const float* b_lin_gen = (const float*)d_in[8];
    const float* W_elin    = (const float*)d_in[9];
    const float* b_elin    = (const float*)d_in[10];
    const float* Wn        = (const float*)d_in[11];
    const float* bn        = (const float*)d_in[12];
    const float* Et        = (const float*)d_in[13];
    const float* Wea       = (const float*)d_in[14];
    const float* Watt      = (const float*)d_in[15];
    const float* Wl        = (const float*)d_in[16];
    const float* bl        = (const float*)d_in[17];
    const float* W_out_bus = (const float*)d_in[18];
    const float* b_out_bus = (const float*)d_in[19];
    const float* W_out_gen = (const float*)d_in[20];
    const float* b_out_gen = (const float*)d_in[21];
    const int*   src       = (const int*)d_in[22];
    const int*   dst       = (const int*)d_in[23];
    const int*   etype     = (const int*)d_in[24];
    float* out = (float*)d_out;

    float *x, *p, *a, *b, *s, *eae, *d, *lg, *Wc, *bc, *va, *vb, *cab, *c3;
    unsigned* m;
    cudaGetSymbolAddress((void**)&x,   g_x);
    cudaGetSymbolAddress((void**)&p,   g_p);
    cudaGetSymbolAddress((void**)&a,   g_a);
    cudaGetSymbolAddress((void**)&b,   g_b);
    cudaGetSymbolAddress((void**)&s,   g_s);
    cudaGetSymbolAddress((void**)&m,   g_m);
    cudaGetSymbolAddress((void**)&eae, g_eae);
    cudaGetSymbolAddress((void**)&d,   g_d);
    cudaGetSymbolAddress((void**)&lg,  g_lg);
    cudaGetSymbolAddress((void**)&Wc,  g_Wc);
    cudaGetSymbolAddress((void**)&bc,  g_bc);
    cudaGetSymbolAddress((void**)&va,  g_va);
    cudaGetSymbolAddress((void**)&vb,  g_vb);
    cudaGetSymbolAddress((void**)&cab, g_cab);
    cudaGetSymbolAddress((void**)&c3,  g_c3);

    // one-time precompute
    prep_weights<<<6, 256>>>(Wn, bn, Wl, bl, Watt, Et);
    embed_nodes<16><<<(NBUS + 3) / 4, 256>>>(x_bus, W_lin_bus, b_lin_bus, x, NBUS);
    embed_nodes<8> <<<(NGEN + 3) / 4, 256>>>(x_gen, W_lin_gen, b_lin_gen, x + (size_t)NBUS * 64, NGEN);
    edge_pre<<<(EE + EPB - 1) / EPB, 256>>>(ea0, ea1, ea2, W_elin, b_elin, Wea, Watt);

    for (int l = 0; l < LAY; l++) {
        int blk = l * 2;
        // fused node GEMM: p, a, b (bus then gen)
        gemm_node<<<(NBUS + 63) / 64, 256>>>(x, Wc + (size_t)blk * 4096, bc + blk * 64,
                                             va + blk * 64, vb + blk * 64, cab + blk * 2,
                                             p, a, b, NBUS);
        gemm_node<<<(NGEN + 63) / 64, 256>>>(x + (size_t)NBUS * 64, Wc + (size_t)(blk + 1) * 4096,
                                             bc + (blk + 1) * 64, va + (blk + 1) * 64,
                                             vb + (blk + 1) * 64, cab + (blk + 1) * 2,
                                             p + (size_t)NBUS * 64, a + NBUS, b + NBUS, NGEN);
        // reset accumulator + softmax state
        zero_kernel<<<(NN * 16 + 2 * NN + 255) / 256, 256>>>((float4*)x, s, m);
        // logits + max
        logit_kernel<<<(EE + 255) / 256, 256>>>(a, b, d + (size_t)l * EE, c3 + l * 3,
                                                src, dst, etype, lg, m);
        // exp + sum
        exp_kernel<<<(EE + 255) / 256, 256>>>(lg, dst, m, s);
        // message + scatter
        const float* Wl2 = Wl + (size_t)l * 80 * 64 + 64 * 64;
        msg_kernel<<<(EE + MEPB - 1) / MEPB, 256>>>(p, eae + (size_t)l * EE * 16, Wl2,
                                                    lg, s, src, dst, x);
    }

    out_kernel<<<((size_t)NN * 32 + 255) / 256, 256>>>(x, W_out_bus, b_out_bus,
                                                       W_out_gen, b_out_gen, out);
}

// round 3
// speedup vs baseline: 2.2519x; 1.2034x over previous
#include <cuda_runtime.h>

#define NBUS 200000
#define NGEN 50000
#define NN   (NBUS + NGEN)
#define EE0  500000
#define EE1  50000
#define EE2  50000
#define EE   (EE0 + EE1 + EE2)
#define LAY  3
#define NEG  0.2f

// ---------------- static device scratch ----------------
__device__ __align__(16) float g_Wc[6][4096];   // folded node weight [l*2+t][k][j]
__device__ float g_bc[6][64];                   // folded node bias
__device__ float g_va[6][64];                   // folded attention vec (dst)
__device__ float g_vb[6][64];                   // folded attention vec (src)
__device__ float g_cab[6][2];                   // folded attention scalars
__device__ float g_c3[9];                       // edge-type logit constants [l][etype]
__device__ __align__(16) float g_x[(size_t)NN * 64];
__device__ __align__(16) float g_p[(size_t)NN * 64];
__device__ float    g_a[NN];
__device__ float    g_b[NN];
__device__ float    g_s[NN];
__device__ __align__(16) float g_eae[(size_t)LAY * EE * 16];
__device__ float g_d [(size_t)LAY * EE];
__device__ float g_lg[EE];

__device__ __forceinline__ float lrelu(float v) { return v >= 0.f ? v : NEG * v; }

// ---------------- weight folding (once per call, 6 blocks) ----------------
__global__ void prep_weights(const float* __restrict__ Wn, const float* __restrict__ bn,
                             const float* __restrict__ Wl, const float* __restrict__ bl,
                             const float* __restrict__ Watt, const float* __restrict__ Et) {
    int blk = blockIdx.x;             // l*2 + t
    int l = blk >> 1, t = blk & 1;
    __shared__ float WnS[4096], Wl1S[4096];
    const float* wn   = Wn + (size_t)blk * 4096;
    const float* wl1  = Wl + (size_t)l * 80 * 64;      // first 64 rows of Wl[l]
    const float* watt = Watt + l * 160;
    const float* bnl  = bn + blk * 64;
    int tid = threadIdx.x;
    for (int i = tid; i < 4096; i += 256) { WnS[i] = wn[i]; Wl1S[i] = wl1[i]; }
    __syncthreads();
    for (int idx = tid; idx < 4096; idx += 256) {
        int k = idx >> 6, j = idx & 63;
        float s = 0.f;
#pragma unroll 8
        for (int m = 0; m < 64; m++) s += WnS[k * 64 + m] * Wl1S[m * 64 + j];
        g_Wc[blk][idx] = s;
    }
    if (tid < 64) {
        int j = tid;
        float s = bl[l * 64 + j];
        for (int m = 0; m < 64; m++) s += bnl[m] * Wl1S[m * 64 + j];
        g_bc[blk][j] = s;
        float sa = 0.f, sb = 0.f;
        for (int m = 0; m < 64; m++) {
            sa += WnS[j * 64 + m] * watt[m];
            sb += WnS[j * 64 + m] * watt[64 + m];
        }
        g_va[blk][j] = sa; g_vb[blk][j] = sb;
    } else if (tid == 64) {
        float ca = 0.f, cb = 0.f;
        for (int m = 0; m < 64; m++) { ca += bnl[m] * watt[m]; cb += bnl[m] * watt[64 + m]; }
        g_cab[blk][0] = ca; g_cab[blk][1] = cb;
    } else if (tid >= 128 && tid < 131 && t == 0) {
        int tt = tid - 128;
        float s = 0.f;
        for (int j = 0; j < 16; j++) s += lrelu(Et[l * 48 + tt * 16 + j]) * watt[128 + j];
        g_c3[l * 3 + tt] = s;
    }
}

// ---------------- node input embed: out = relu(xin @ W + b) ----------------
template <int K>
__global__ void embed_nodes(const float* __restrict__ xin, const float* __restrict__ W,
                            const float* __restrict__ bias, float* __restrict__ xout, int rows) {
    __shared__ float Ws[K * 64];
    __shared__ float bs[64];
    __shared__ float xs[4 * K];
    int tid = threadIdx.x;
    for (int i = tid; i < K * 64; i += 256) Ws[i] = W[i];
    if (tid < 64) bs[tid] = bias[tid];
    int base = blockIdx.x * 4;
    for (int i = tid; i < 4 * K; i += 256) {
        int r = base + i / K;
        xs[i] = (r < rows) ? xin[(size_t)base * K + i] : 0.f;
    }
    __syncthreads();
    int j = tid & 63, s = tid >> 6;
    int n = base + s;
    if (n < rows) {
        float acc = bs[j];
#pragma unroll
        for (int k = 0; k < K; k++) acc += xs[s * K + k] * Ws[k * 64 + j];
        xout[(size_t)n * 64 + j] = fmaxf(acc, 0.f);
    }
}

// ---------------- edge precompute: eae[l], d[l] for all 3 layers (once) ----------------
// 64 edges per block; phase 2 register-caches the edge row and uses float4 LDS.
#define EPB 64
__global__ void edge_pre(const float* __restrict__ ea0, const float* __restrict__ ea1,
                         const float* __restrict__ ea2, const float* __restrict__ W_elin,
                         const float* __restrict__ b_elin, const float* __restrict__ Wea,
                         const float* __restrict__ Watt) {
    __shared__ float We[1728];         // [t][k][64]
    __shared__ float be[192];
    __shared__ float WeaS[3072];       // [l][m][16]
    __shared__ float w4s[48];          // [l][16]
    __shared__ float raw[EPB * 9];
    __shared__ __align__(16) float ea64[EPB * 68];   // row stride 68 (16B-aligned, bank-spread)
    int tid = threadIdx.x;
    for (int i = tid; i < 1728; i += 256) We[i] = W_elin[i];
    if (tid < 192) be[tid] = b_elin[tid];
    for (int i = tid; i < 3072; i += 256) WeaS[i] = Wea[i];
    if (tid < 48) w4s[tid] = Watt[(tid >> 4) * 160 + 144 + (tid & 15)];
    int base = blockIdx.x * EPB;   // EE % EPB == 0
    for (int i = tid; i < EPB * 9; i += 256) {
        int e = base + i / 9, k = i % 9;
        float v;
        if (e < EE0)            v = ea0[(size_t)e * 9 + k];
        else if (e < EE0 + EE1) v = ea1[(size_t)(e - EE0) * 9 + k];
        else                    v = ea2[(size_t)(e - EE0 - EE1) * 9 + k];
        raw[i] = v;
    }
    __syncthreads();
    // phase 1: ea64 = relu(raw @ W_elin[type] + b), float4 over j
    for (int idx = tid; idx < EPB * 16; idx += 256) {
        int s = idx >> 4, cx = idx & 15;
        int e = base + s;
        int t = (e < EE0) ? 0 : ((e < EE0 + EE1) ? 1 : 2);
        float4 acc = ((const float4*)be)[t * 16 + cx];
#pragma unroll
        for (int k = 0; k < 9; k++) {
            float rv = raw[s * 9 + k];
            float4 wv = ((const float4*)We)[(t * 9 + k) * 16 + cx];
            acc.x += rv * wv.x; acc.y += rv * wv.y; acc.z += rv * wv.z; acc.w += rv * wv.w;
        }
        acc.x = fmaxf(acc.x, 0.f); acc.y = fmaxf(acc.y, 0.f);
        acc.z = fmaxf(acc.z, 0.f); acc.w = fmaxf(acc.w, 0.f);
        *(float4*)&ea64[s * 68 + cx * 4] = acc;
    }
    __syncthreads();
    // phase 2: per layer eae16 = leaky(ea64 @ Wea[l]), d = eae16 . w4
    int row = tid >> 2, tx = tid & 3;
    int e = base + row;
    const float4* ea4 = (const float4*)&ea64[row * 68];
    float4 ev[16];
#pragma unroll
    for (int mm = 0; mm < 16; mm++) ev[mm] = ea4[mm];
#pragma unroll
    for (int l = 0; l < 3; l++) {
        const float4* W4 = (const float4*)&WeaS[l * 1024];   // [m][4 float4], idx m*4+tx
        float4 acc = make_float4(0.f, 0.f, 0.f, 0.f);
#pragma unroll
        for (int mm = 0; mm < 16; mm++) {
            float4 e4 = ev[mm];
            float4 w0 = W4[(4 * mm + 0) * 4 + tx];
            float4 w1 = W4[(4 * mm + 1) * 4 + tx];
            float4 w2 = W4[(4 * mm + 2) * 4 + tx];
            float4 w3 = W4[(4 * mm + 3) * 4 + tx];
            acc.x += e4.x * w0.x + e4.y * w1.x + e4.z * w2.x + e4.w * w3.x;
            acc.y += e4.x * w0.y + e4.y * w1.y + e4.z * w2.y + e4.w * w3.y;
            acc.z += e4.x * w0.z + e4.y * w1.z + e4.z * w2.z + e4.w * w3.z;
            acc.w += e4.x * w0.w + e4.y * w1.w + e4.z * w2.w + e4.w * w3.w;
        }
        acc.x = lrelu(acc.x); acc.y = lrelu(acc.y); acc.z = lrelu(acc.z); acc.w = lrelu(acc.w);
        ((float4*)g_eae)[((size_t)l * EE + e) * 4 + tx] = acc;
        float4 wv = ((const float4*)w4s)[l * 4 + tx];
        float dd = acc.x * wv.x + acc.y * wv.y + acc.z * wv.z + acc.w * wv.w;
        dd += __shfl_down_sync(0xffffffffu, dd, 2, 4);
        dd += __shfl_down_sync(0xffffffffu, dd, 1, 4);
        if (tx == 0) g_d[(size_t)l * EE + e] = dd;
    }
}

// ---------------- fused node GEMM: p = relu(x)@Wc + bc, a/b = relu(x).va/vb + c ----------------
__global__ void gemm_node(const float* __restrict__ x, const float* __restrict__ Wc,
                          const float* __restrict__ bc, const float* __restrict__ va,
                          const float* __restrict__ vb, const float* __restrict__ cab,
                          float* __restrict__ p, float* __restrict__ a, float* __restrict__ b,
                          int rows) {
    __shared__ float Ws[4096];            // [k][j]
    __shared__ float xsT[64 * 68];        // [k][row]
    __shared__ float vas[64], vbs[64], bcs[64];
    int tid = threadIdx.x;
    for (int i = tid; i < 4096; i += 256) Ws[i] = Wc[i];
    if (tid < 64) { vas[tid] = va[tid]; vbs[tid] = vb[tid]; bcs[tid] = bc[tid]; }
    int base = blockIdx.x * 64;
    int cnt = min(64, rows - base);
    for (int idx = tid; idx < 4096; idx += 256) {
        int r = idx >> 6, k = idx & 63;
        float v = (r < cnt) ? fmaxf(x[(size_t)(base + r) * 64 + k], 0.f) : 0.f;
        xsT[k * 68 + r] = v;
    }
    __syncthreads();
    int ty = tid >> 4, tx = tid & 15;
    float4 acc0, acc1, acc2, acc3;
    {
        float4 bc4 = ((const float4*)bcs)[tx];
        acc0 = bc4; acc1 = bc4; acc2 = bc4; acc3 = bc4;
    }
#pragma unroll 8
    for (int k = 0; k < 64; k++) {
        float4 av = *(const float4*)&xsT[k * 68 + 4 * ty];
        float4 wv = ((const float4*)Ws)[k * 16 + tx];
        acc0.x += av.x * wv.x; acc0.y += av.x * wv.y; acc0.z += av.x * wv.z; acc0.w += av.x * wv.w;
        acc1.x += av.y * wv.x; acc1.y += av.y * wv.y; acc1.z += av.y * wv.z; acc1.w += av.y * wv.w;
        acc2.x += av.z * wv.x; acc2.y += av.z * wv.y; acc2.z += av.z * wv.z; acc2.w += av.z * wv.w;
        acc3.x += av.w * wv.x; acc3.y += av.w * wv.y; acc3.z += av.w * wv.z; acc3.w += av.w * wv.w;
    }
    float4* p4 = (float4*)p;
    int r0 = 4 * ty;
    if (r0 + 0 < cnt) p4[(size_t)(base + r0 + 0) * 16 + tx] = acc0;
    if (r0 + 1 < cnt) p4[(size_t)(base + r0 + 1) * 16 + tx] = acc1;
    if (r0 + 2 < cnt) p4[(size_t)(base + r0 + 2) * 16 + tx] = acc2;
    if (r0 + 3 < cnt) p4[(size_t)(base + r0 + 3) * 16 + tx] = acc3;
    int row = tid >> 2, q = tid & 3;
    float pa = 0.f, pb = 0.f;
#pragma unroll
    for (int kk = 0; kk < 16; kk++) {
        int k = q * 16 + kk;
        float v = xsT[k * 68 + row];
        pa += v * vas[k]; pb += v * vbs[k];
    }
#pragma unroll
    for (int off = 2; off; off >>= 1) {
        pa += __shfl_down_sync(0xffffffffu, pa, off, 4);
        pb += __shfl_down_sync(0xffffffffu, pb, off, 4);
    }
    if (q == 0 && row < cnt) {
        a[base + row] = pa + cab[0];
        b[base + row] = pb + cab[1];
    }
}

// ---------------- zero accumulator + softmax denominator ----------------
__global__ void zero_kernel(float4* __restrict__ x4, float* __restrict__ s) {
    int i = blockIdx.x * 256 + threadIdx.x;
    if (i < NN * 16) { x4[i] = make_float4(0.f, 0.f, 0.f, 0.f); return; }
    int r = i - NN * 16;
    if (r < NN) s[r] = 0.f;
}

// ---------------- logits + exp + segment sum (no max: |logit| << 1) ----------------
__global__ void logitexp_kernel(const float* __restrict__ a, const float* __restrict__ b,
                                const float* __restrict__ d, const float* __restrict__ c3,
                                const int* __restrict__ src, const int* __restrict__ dst,
                                const int* __restrict__ etype,
                                float* __restrict__ lg, float* __restrict__ s) {
    int e = blockIdx.x * 256 + threadIdx.x;
    if (e >= EE) return;
    int de = dst[e];
    float v = lrelu(a[de] + b[src[e]] + c3[etype[e]] + d[e]);
    float f = expf(v);
    lg[e] = f;
    atomicAdd(&s[de], f);
}

// ---------------- message + vectorized scatter ----------------
#define MEPB 64
__global__ void msg_kernel(const float* __restrict__ p, const float* __restrict__ eae,
                           const float* __restrict__ Wl2, const float* __restrict__ ex,
                           const float* __restrict__ ssum, const int* __restrict__ src,
                           const int* __restrict__ dst, float* __restrict__ accum) {
    __shared__ float Wl2S[1024];          // [k][j] 16x64
    __shared__ float eaes[16][16];
    int tid = threadIdx.x;
    for (int i = tid; i < 1024; i += 256) Wl2S[i] = Wl2[i];
    int s = tid >> 4, t = tid & 15;
#pragma unroll
    for (int pass = 0; pass < MEPB / 16; pass++) {
        int base = blockIdx.x * MEPB + pass * 16;
        __syncthreads();
        {
            int e = base + (tid >> 4);
            eaes[tid >> 4][tid & 15] = (e < EE) ? eae[(size_t)e * 16 + (tid & 15)] : 0.f;
        }
        __syncthreads();
        int e = base + s;
        if (e < EE) {
            int de = dst[e], se = src[e];
            float alpha = ex[e] / (ssum[de] + 1e-16f);
            float4 acc = ((const float4*)p)[(size_t)se * 16 + t];
#pragma unroll
            for (int k = 0; k < 16; k++) {
                float evv = eaes[s][k];
                float4 wv = ((const float4*)Wl2S)[k * 16 + t];
                acc.x += evv * wv.x; acc.y += evv * wv.y; acc.z += evv * wv.z; acc.w += evv * wv.w;
            }
            acc.x *= alpha; acc.y *= alpha; acc.z *= alpha; acc.w *= alpha;
            float* addr = accum + (size_t)de * 64 + 4 * t;
            asm volatile("red.global.add.v4.f32 [%0], {%1, %2, %3, %4};"
                         :: "l"(addr), "f"(acc.x), "f"(acc.y), "f"(acc.z), "f"(acc.w)
                         : "memory");
        }
    }
}

// ---------------- output: sigmoid(relu(x) @ W_out + b) ----------------
__global__ void out_kernel(const float* __restrict__ x, const float* __restrict__ Wb,
                           const float* __restrict__ bb, const float* __restrict__ Wg,
                           const float* __restrict__ bg, float* __restrict__ out) {
    int gt = blockIdx.x * 256 + threadIdx.x;
    int n = gt >> 5, lane = gt & 31;
    if (n >= NN) return;
    float v0 = fmaxf(x[(size_t)n * 64 + lane], 0.f);
    float v1 = fmaxf(x[(size_t)n * 64 + 32 + lane], 0.f);
    const float* W = (n < NBUS) ? Wb : Wg;
    float a0 = v0 * __ldg(&W[lane * 2])     + v1 * __ldg(&W[(lane + 32) * 2]);
    float a1 = v0 * __ldg(&W[lane * 2 + 1]) + v1 * __ldg(&W[(lane + 32) * 2 + 1]);
#pragma unroll
    for (int off = 16; off; off >>= 1) {
        a0 += __shfl_down_sync(0xffffffffu, a0, off);
        a1 += __shfl_down_sync(0xffffffffu, a1, off);
    }
    if (lane == 0) {
        const float* bias = (n < NBUS) ? bb : bg;
        float z0 = a0 + bias[0], z1 = a1 + bias[1];
        out[(size_t)n * 2 + 0] = 1.f / (1.f + expf(-z0));
        out[(size_t)n * 2 + 1] = 1.f / (1.f + expf(-z1));
    }
}

// ---------------- host launcher ----------------
extern "C" void kernel_launch(void* const* d_in, const int* in_sizes, int n_in,
                              void* d_out, int out_size) {
    const float* x_bus     = (const float*)d_in[0];
    const float* x_gen     = (const float*)d_in[1];
    const float* ea0       = (const float*)d_in[2];
    const float* ea1       = (const float*)d_in[3];
    const float* ea2       = (const float*)d_in[4];
    const float* W_lin_bus = (const float*)d_in[5];
    const float* b_lin_bus = (const float*)d_in[6];
    const float* W_lin_gen = (const float*)d_in[7];
    const float* b_lin_gen = (const float*)d_in[8];
    const float* W_elin    = (const float*)d_in[9];
    const float* b_elin    = (const float*)d_in[10];
    const float* Wn        = (const float*)d_in[11];
    const float* bn        = (const float*)d_in[12];
    const float* Et        = (const float*)d_in[13];
    const float* Wea       = (const float*)d_in[14];
    const float* Watt      = (const float*)d_in[15];
    const float* Wl        = (const float*)d_in[16];
    const float* bl        = (const float*)d_in[17];
    const float* W_out_bus = (const float*)d_in[18];
    const float* b_out_bus = (const float*)d_in[19];
    const float* W_out_gen = (const float*)d_in[20];
    const float* b_out_gen = (const float*)d_in[21];
    const int*   src       = (const int*)d_in[22];
    const int*   dst       = (const int*)d_in[23];
    const int*   etype     = (const int*)d_in[24];
    float* out = (float*)d_out;

    float *x, *p, *a, *b, *s, *eae, *d, *lg, *Wc, *bc, *va, *vb, *cab, *c3;
    cudaGetSymbolAddress((void**)&x,   g_x);
    cudaGetSymbolAddress((void**)&p,   g_p);
    cudaGetSymbolAddress((void**)&a,   g_a);
    cudaGetSymbolAddress((void**)&b,   g_b);
    cudaGetSymbolAddress((void**)&s,   g_s);
    cudaGetSymbolAddress((void**)&eae, g_eae);
    cudaGetSymbolAddress((void**)&d,   g_d);
    cudaGetSymbolAddress((void**)&lg,  g_lg);
    cudaGetSymbolAddress((void**)&Wc,  g_Wc);
    cudaGetSymbolAddress((void**)&bc,  g_bc);
    cudaGetSymbolAddress((void**)&va,  g_va);
    cudaGetSymbolAddress((void**)&vb,  g_vb);
    cudaGetSymbolAddress((void**)&cab, g_cab);
    cudaGetSymbolAddress((void**)&c3,  g_c3);

    // one-time precompute
    prep_weights<<<6, 256>>>(Wn, bn, Wl, bl, Watt, Et);
    embed_nodes<16><<<(NBUS + 3) / 4, 256>>>(x_bus, W_lin_bus, b_lin_bus, x, NBUS);
    embed_nodes<8> <<<(NGEN + 3) / 4, 256>>>(x_gen, W_lin_gen, b_lin_gen, x + (size_t)NBUS * 64, NGEN);
    edge_pre<<<EE / EPB, 256>>>(ea0, ea1, ea2, W_elin, b_elin, Wea, Watt);

    for (int l = 0; l < LAY; l++) {
        int blk = l * 2;
        gemm_node<<<(NBUS + 63) / 64, 256>>>(x, Wc + (size_t)blk * 4096, bc + blk * 64,
                                             va + blk * 64, vb + blk * 64, cab + blk * 2,
                                             p, a, b, NBUS);
        gemm_node<<<(NGEN + 63) / 64, 256>>>(x + (size_t)NBUS * 64, Wc + (size_t)(blk + 1) * 4096,
                                             bc + (blk + 1) * 64, va + (blk + 1) * 64,
                                             vb + (blk + 1) * 64, cab + (blk + 1) * 2,
                                             p + (size_t)NBUS * 64, a + NBUS, b + NBUS, NGEN);
        zero_kernel<<<(NN * 16 + NN + 255) / 256, 256>>>((float4*)x, s);
        logitexp_kernel<<<(EE + 255) / 256, 256>>>(a, b, d + (size_t)l * EE, c3 + l * 3,
                                                   src, dst, etype, lg, s);
        const float* Wl2 = Wl + (size_t)l * 80 * 64 + 64 * 64;
        msg_kernel<<<(EE + MEPB - 1) / MEPB, 256>>>(p, eae + (size_t)l * EE * 16, Wl2,
                                                    lg, s, src, dst, x);
    }

    out_kernel<<<((size_t)NN * 32 + 255) / 256, 256>>>(x, W_out_bus, b_out_bus,
                                                       W_out_gen, b_out_gen, out);
}

// round 4
// speedup vs baseline: 2.4128x; 1.0715x over previous
#include <cuda_runtime.h>

#define NBUS 200000
#define NGEN 50000
#define NN   (NBUS + NGEN)
#define EE0  500000
#define EE1  50000
#define EE2  50000
#define EE   (EE0 + EE1 + EE2)
#define LAY  3
#define NEG  0.2f

// ---------------- static device scratch ----------------
__device__ __align__(16) float g_Wc[6][4096];   // folded node weight [l*2+t][k][j]
__device__ float g_bc[6][64];                   // folded node bias
__device__ float g_va[6][64];                   // folded attention vec (dst)
__device__ float g_vb[6][64];                   // folded attention vec (src)
__device__ float g_cab[6][2];                   // folded attention scalars
__device__ float g_c3[9];                       // edge-type logit constants [l][etype]
__device__ __align__(16) float g_x[(size_t)NN * 64];   // unnormalized aggregate
__device__ __align__(16) float g_p[(size_t)NN * 64];
__device__ float g_a[NN];
__device__ float g_b[NN];
__device__ float g_s[NN];                       // softmax denominator (sum of exp)
__device__ __align__(16) float g_eae[(size_t)LAY * EE * 16];
__device__ float g_d[(size_t)LAY * EE];

__device__ __forceinline__ float lrelu(float v) { return v >= 0.f ? v : NEG * v; }

// ---------------- weight folding (once per call, 6 blocks) ----------------
__global__ void prep_weights(const float* __restrict__ Wn, const float* __restrict__ bn,
                             const float* __restrict__ Wl, const float* __restrict__ bl,
                             const float* __restrict__ Watt, const float* __restrict__ Et) {
    int blk = blockIdx.x;             // l*2 + t
    int l = blk >> 1, t = blk & 1;
    __shared__ float WnS[4096], Wl1S[4096];
    const float* wn   = Wn + (size_t)blk * 4096;
    const float* wl1  = Wl + (size_t)l * 80 * 64;
    const float* watt = Watt + l * 160;
    const float* bnl  = bn + blk * 64;
    int tid = threadIdx.x;
    for (int i = tid; i < 4096; i += 256) { WnS[i] = wn[i]; Wl1S[i] = wl1[i]; }
    __syncthreads();
    for (int idx = tid; idx < 4096; idx += 256) {
        int k = idx >> 6, j = idx & 63;
        float s = 0.f;
#pragma unroll 8
        for (int m = 0; m < 64; m++) s += WnS[k * 64 + m] * Wl1S[m * 64 + j];
        g_Wc[blk][idx] = s;
    }
    if (tid < 64) {
        int j = tid;
        float s = bl[l * 64 + j];
        for (int m = 0; m < 64; m++) s += bnl[m] * Wl1S[m * 64 + j];
        g_bc[blk][j] = s;
        float sa = 0.f, sb = 0.f;
        for (int m = 0; m < 64; m++) {
            sa += WnS[j * 64 + m] * watt[m];
            sb += WnS[j * 64 + m] * watt[64 + m];
        }
        g_va[blk][j] = sa; g_vb[blk][j] = sb;
    } else if (tid == 64) {
        float ca = 0.f, cb = 0.f;
        for (int m = 0; m < 64; m++) { ca += bnl[m] * watt[m]; cb += bnl[m] * watt[64 + m]; }
        g_cab[blk][0] = ca; g_cab[blk][1] = cb;
    } else if (tid >= 128 && tid < 131 && t == 0) {
        int tt = tid - 128;
        float s = 0.f;
        for (int j = 0; j < 16; j++) s += lrelu(Et[l * 48 + tt * 16 + j]) * watt[128 + j];
        g_c3[l * 3 + tt] = s;
    }
}

// ---------------- node input embed: out = relu(xin @ W + b) ----------------
template <int K>
__global__ void embed_nodes(const float* __restrict__ xin, const float* __restrict__ W,
                            const float* __restrict__ bias, float* __restrict__ xout, int rows) {
    __shared__ float Ws[K * 64];
    __shared__ float bs[64];
    __shared__ float xs[4 * K];
    int tid = threadIdx.x;
    for (int i = tid; i < K * 64; i += 256) Ws[i] = W[i];
    if (tid < 64) bs[tid] = bias[tid];
    int base = blockIdx.x * 4;
    for (int i = tid; i < 4 * K; i += 256) {
        int r = base + i / K;
        xs[i] = (r < rows) ? xin[(size_t)base * K + i] : 0.f;
    }
    __syncthreads();
    int j = tid & 63, s = tid >> 6;
    int n = base + s;
    if (n < rows) {
        float acc = bs[j];
#pragma unroll
        for (int k = 0; k < K; k++) acc += xs[s * K + k] * Ws[k * 64 + j];
        xout[(size_t)n * 64 + j] = fmaxf(acc, 0.f);
    }
}

// ---------------- edge precompute: eae[l], d[l] via 64x48x64 register-tiled GEMM ----------------
#define EPB 64
__global__ void edge_pre(const float* __restrict__ ea0, const float* __restrict__ ea1,
                         const float* __restrict__ ea2, const float* __restrict__ W_elin,
                         const float* __restrict__ b_elin, const float* __restrict__ Wea,
                         const float* __restrict__ Watt) {
    __shared__ float We[1728];                  // [t][k][64]
    __shared__ float be[192];
    __shared__ __align__(16) float Wcat[4096];  // [k][64]: cols l*16+q (48 used)
    __shared__ float w4s[64];                   // [l][16] (+pad)
    __shared__ float raw[EPB * 9];
    __shared__ __align__(16) float eaT[64 * 68]; // [k][row]
    int tid = threadIdx.x;
    for (int i = tid; i < 1728; i += 256) We[i] = W_elin[i];
    if (tid < 192) be[tid] = b_elin[tid];
    for (int i = tid; i < 3072; i += 256) {      // Wea[l][m][16] -> Wcat[m][l*16+q]
        int l = i >> 10, rem = i & 1023, m = rem >> 4, q = rem & 15;
        Wcat[m * 64 + l * 16 + q] = Wea[i];
    }
    for (int i = tid; i < 1024; i += 256) {      // zero pad cols 48..63
        int m = i >> 4, q = i & 15;
        Wcat[m * 64 + 48 + q] = 0.f;
    }
    if (tid < 48) w4s[tid] = Watt[(tid >> 4) * 160 + 144 + (tid & 15)];
    else if (tid < 64) w4s[tid] = 0.f;
    int base = blockIdx.x * EPB;                 // EE % EPB == 0
    for (int i = tid; i < EPB * 9; i += 256) {
        int e = base + i / 9, k = i % 9;
        float v;
        if (e < EE0)            v = ea0[(size_t)e * 9 + k];
        else if (e < EE0 + EE1) v = ea1[(size_t)(e - EE0) * 9 + k];
        else                    v = ea2[(size_t)(e - EE0 - EE1) * 9 + k];
        raw[i] = v;
    }
    __syncthreads();
    // phase 1: ea64 = relu(raw @ W_elin[type] + b), stored transposed [k][row]
    for (int idx = tid; idx < EPB * 16; idx += 256) {
        int s = idx >> 4, cx = idx & 15;
        int e = base + s;
        int t = (e < EE0) ? 0 : ((e < EE0 + EE1) ? 1 : 2);
        float4 acc = ((const float4*)be)[t * 16 + cx];
#pragma unroll
        for (int k = 0; k < 9; k++) {
            float rv = raw[s * 9 + k];
            float4 wv = ((const float4*)We)[(t * 9 + k) * 16 + cx];
            acc.x += rv * wv.x; acc.y += rv * wv.y; acc.z += rv * wv.z; acc.w += rv * wv.w;
        }
        eaT[(4 * cx + 0) * 68 + s] = fmaxf(acc.x, 0.f);
        eaT[(4 * cx + 1) * 68 + s] = fmaxf(acc.y, 0.f);
        eaT[(4 * cx + 2) * 68 + s] = fmaxf(acc.z, 0.f);
        eaT[(4 * cx + 3) * 68 + s] = fmaxf(acc.w, 0.f);
    }
    __syncthreads();
    // phase 2: C[64 rows][64 cols] = eaT^T @ Wcat, 4x4 tile per thread
    int ty = tid >> 4, tx = tid & 15;
    float4 acc0 = make_float4(0.f,0.f,0.f,0.f), acc1 = acc0, acc2 = acc0, acc3 = acc0;
#pragma unroll 8
    for (int k = 0; k < 64; k++) {
        float4 av = *(const float4*)&eaT[k * 68 + 4 * ty];
        float4 wv = ((const float4*)Wcat)[k * 16 + tx];
        acc0.x += av.x * wv.x; acc0.y += av.x * wv.y; acc0.z += av.x * wv.z; acc0.w += av.x * wv.w;
        acc1.x += av.y * wv.x; acc1.y += av.y * wv.y; acc1.z += av.y * wv.z; acc1.w += av.y * wv.w;
        acc2.x += av.z * wv.x; acc2.y += av.z * wv.y; acc2.z += av.z * wv.z; acc2.w += av.z * wv.w;
        acc3.x += av.w * wv.x; acc3.y += av.w * wv.y; acc3.z += av.w * wv.z; acc3.w += av.w * wv.w;
    }
    // leaky relu
    acc0.x = lrelu(acc0.x); acc0.y = lrelu(acc0.y); acc0.z = lrelu(acc0.z); acc0.w = lrelu(acc0.w);
    acc1.x = lrelu(acc1.x); acc1.y = lrelu(acc1.y); acc1.z = lrelu(acc1.z); acc1.w = lrelu(acc1.w);
    acc2.x = lrelu(acc2.x); acc2.y = lrelu(acc2.y); acc2.z = lrelu(acc2.z); acc2.w = lrelu(acc2.w);
    acc3.x = lrelu(acc3.x); acc3.y = lrelu(acc3.y); acc3.z = lrelu(acc3.z); acc3.w = lrelu(acc3.w);
    int l = tx >> 2, q = tx & 3;
    int r0 = base + 4 * ty;
    if (tx < 12) {
        float4* eo = (float4*)g_eae;
        eo[((size_t)l * EE + r0 + 0) * 4 + q] = acc0;
        eo[((size_t)l * EE + r0 + 1) * 4 + q] = acc1;
        eo[((size_t)l * EE + r0 + 2) * 4 + q] = acc2;
        eo[((size_t)l * EE + r0 + 3) * 4 + q] = acc3;
    }
    // d = eae . w4, reduce over the 4 lanes of each layer-column group
    float4 wv = ((const float4*)w4s)[((tx < 12) ? l : 0) * 4 + q];
    float d0 = acc0.x * wv.x + acc0.y * wv.y + acc0.z * wv.z + acc0.w * wv.w;
    float d1 = acc1.x * wv.x + acc1.y * wv.y + acc1.z * wv.z + acc1.w * wv.w;
    float d2 = acc2.x * wv.x + acc2.y * wv.y + acc2.z * wv.z + acc2.w * wv.w;
    float d3 = acc3.x * wv.x + acc3.y * wv.y + acc3.z * wv.z + acc3.w * wv.w;
#pragma unroll
    for (int off = 2; off; off >>= 1) {
        d0 += __shfl_down_sync(0xffffffffu, d0, off, 4);
        d1 += __shfl_down_sync(0xffffffffu, d1, off, 4);
        d2 += __shfl_down_sync(0xffffffffu, d2, off, 4);
        d3 += __shfl_down_sync(0xffffffffu, d3, off, 4);
    }
    if (q == 0 && tx < 12) {
        g_d[(size_t)l * EE + r0 + 0] = d0;
        g_d[(size_t)l * EE + r0 + 1] = d1;
        g_d[(size_t)l * EE + r0 + 2] = d2;
        g_d[(size_t)l * EE + r0 + 3] = d3;
    }
}

// ---------------- fused node GEMM: p = relu(x/s)@Wc + bc, a/b scalars ----------------
__global__ void gemm_node(const float* __restrict__ x, const float* __restrict__ sden,
                          int use_s, const float* __restrict__ Wc,
                          const float* __restrict__ bc, const float* __restrict__ va,
                          const float* __restrict__ vb, const float* __restrict__ cab,
                          float* __restrict__ p, float* __restrict__ a, float* __restrict__ b,
                          int rows) {
    __shared__ float Ws[4096];            // [k][j]
    __shared__ float xsT[64 * 68];        // [k][row]
    __shared__ float vas[64], vbs[64], bcs[64], sdiv[64];
    int tid = threadIdx.x;
    int base = blockIdx.x * 64;
    int cnt = min(64, rows - base);
    for (int i = tid; i < 4096; i += 256) Ws[i] = Wc[i];
    if (tid < 64) {
        vas[tid] = va[tid]; vbs[tid] = vb[tid]; bcs[tid] = bc[tid];
        float sv = 1.f;
        if (use_s && tid < cnt) sv = 1.f / (sden[base + tid] + 1e-16f);
        sdiv[tid] = sv;
    }
    __syncthreads();
    for (int idx = tid; idx < 4096; idx += 256) {
        int r = idx >> 6, k = idx & 63;
        float v = (r < cnt) ? fmaxf(x[(size_t)(base + r) * 64 + k], 0.f) * sdiv[r] : 0.f;
        xsT[k * 68 + r] = v;
    }
    __syncthreads();
    int ty = tid >> 4, tx = tid & 15;
    float4 acc0, acc1, acc2, acc3;
    {
        float4 bc4 = ((const float4*)bcs)[tx];
        acc0 = bc4; acc1 = bc4; acc2 = bc4; acc3 = bc4;
    }
#pragma unroll 8
    for (int k = 0; k < 64; k++) {
        float4 av = *(const float4*)&xsT[k * 68 + 4 * ty];
        float4 wv = ((const float4*)Ws)[k * 16 + tx];
        acc0.x += av.x * wv.x; acc0.y += av.x * wv.y; acc0.z += av.x * wv.z; acc0.w += av.x * wv.w;
        acc1.x += av.y * wv.x; acc1.y += av.y * wv.y; acc1.z += av.y * wv.z; acc1.w += av.y * wv.w;
        acc2.x += av.z * wv.x; acc2.y += av.z * wv.y; acc2.z += av.z * wv.z; acc2.w += av.z * wv.w;
        acc3.x += av.w * wv.x; acc3.y += av.w * wv.y; acc3.z += av.w * wv.z; acc3.w += av.w * wv.w;
    }
    float4* p4 = (float4*)p;
    int r0 = 4 * ty;
    if (r0 + 0 < cnt) p4[(size_t)(base + r0 + 0) * 16 + tx] = acc0;
    if (r0 + 1 < cnt) p4[(size_t)(base + r0 + 1) * 16 + tx] = acc1;
    if (r0 + 2 < cnt) p4[(size_t)(base + r0 + 2) * 16 + tx] = acc2;
    if (r0 + 3 < cnt) p4[(size_t)(base + r0 + 3) * 16 + tx] = acc3;
    int row = tid >> 2, q = tid & 3;
    float pa = 0.f, pb = 0.f;
#pragma unroll
    for (int kk = 0; kk < 16; kk++) {
        int k = q * 16 + kk;
        float v = xsT[k * 68 + row];
        pa += v * vas[k]; pb += v * vbs[k];
    }
#pragma unroll
    for (int off = 2; off; off >>= 1) {
        pa += __shfl_down_sync(0xffffffffu, pa, off, 4);
        pb += __shfl_down_sync(0xffffffffu, pb, off, 4);
    }
    if (q == 0 && row < cnt) {
        a[base + row] = pa + cab[0];
        b[base + row] = pb + cab[1];
    }
}

// ---------------- zero accumulator + softmax denominator ----------------
__global__ void zero_kernel(float4* __restrict__ x4, float* __restrict__ s) {
    int i = blockIdx.x * 256 + threadIdx.x;
    if (i < NN * 16) { x4[i] = make_float4(0.f, 0.f, 0.f, 0.f); return; }
    int r = i - NN * 16;
    if (r < NN) s[r] = 0.f;
}

// ---------------- fused edge pass: logit + exp + unnormalized message scatter ----------------
#define MEPB 64
__global__ void edge_fused(const float* __restrict__ a, const float* __restrict__ b,
                           const float* __restrict__ d, const float* __restrict__ c3l,
                           const float* __restrict__ p, const float* __restrict__ eae,
                           const float* __restrict__ Wl2, const int* __restrict__ src,
                           const int* __restrict__ dst, float* __restrict__ x,
                           float* __restrict__ s) {
    __shared__ float Wl2S[1024];          // [k][j] 16x64
    __shared__ float eaes[16][17];
    int tid = threadIdx.x;
    for (int i = tid; i < 1024; i += 256) Wl2S[i] = Wl2[i];
    float c0 = __ldg(&c3l[0]), c1 = __ldg(&c3l[1]), c2 = __ldg(&c3l[2]);
    int sg = tid >> 4, t = tid & 15;
#pragma unroll
    for (int pass = 0; pass < MEPB / 16; pass++) {
        int base = blockIdx.x * MEPB + pass * 16;   // EE % MEPB == 0
        __syncthreads();
        eaes[sg][t] = eae[(size_t)(base + sg) * 16 + t];
        __syncthreads();
        int e = base + sg;
        int de = dst[e], se = src[e];
        float c = (e < EE0) ? c0 : ((e < EE0 + EE1) ? c1 : c2);
        float lg = lrelu(a[de] + b[se] + c + d[e]);
        float ex = __expf(lg);
        float4 acc = ((const float4*)p)[(size_t)se * 16 + t];
#pragma unroll
        for (int k = 0; k < 16; k++) {
            float evv = eaes[sg][k];
            float4 wv = ((const float4*)Wl2S)[k * 16 + t];
            acc.x += evv * wv.x; acc.y += evv * wv.y; acc.z += evv * wv.z; acc.w += evv * wv.w;
        }
        acc.x *= ex; acc.y *= ex; acc.z *= ex; acc.w *= ex;
        float* addr = x + (size_t)de * 64 + 4 * t;
        asm volatile("red.global.add.v4.f32 [%0], {%1, %2, %3, %4};"
                     :: "l"(addr), "f"(acc.x), "f"(acc.y), "f"(acc.z), "f"(acc.w)
                     : "memory");
        if (t == 0) atomicAdd(&s[de], ex);
    }
}

// ---------------- output: sigmoid((relu(x)/s) @ W_out + b) ----------------
__global__ void out_kernel(const float* __restrict__ x, const float* __restrict__ sden,
                           const float* __restrict__ Wb, const float* __restrict__ bb,
                           const float* __restrict__ Wg, const float* __restrict__ bg,
                           float* __restrict__ out) {
    int gt = blockIdx.x * 256 + threadIdx.x;
    int n = gt >> 5, lane = gt & 31;
    if (n >= NN) return;
    float sinv = 1.f / (sden[n] + 1e-16f);
    float v0 = fmaxf(x[(size_t)n * 64 + lane], 0.f) * sinv;
    float v1 = fmaxf(x[(size_t)n * 64 + 32 + lane], 0.f) * sinv;
    const float* W = (n < NBUS) ? Wb : Wg;
    float a0 = v0 * __ldg(&W[lane * 2])     + v1 * __ldg(&W[(lane + 32) * 2]);
    float a1 = v0 * __ldg(&W[lane * 2 + 1]) + v1 * __ldg(&W[(lane + 32) * 2 + 1]);
#pragma unroll
    for (int off = 16; off; off >>= 1) {
        a0 += __shfl_down_sync(0xffffffffu, a0, off);
        a1 += __shfl_down_sync(0xffffffffu, a1, off);
    }
    if (lane == 0) {
        const float* bias = (n < NBUS) ? bb : bg;
        float z0 = a0 + bias[0], z1 = a1 + bias[1];
        out[(size_t)n * 2 + 0] = 1.f / (1.f + __expf(-z0));
        out[(size_t)n * 2 + 1] = 1.f / (1.f + __expf(-z1));
    }
}

// ---------------- host launcher ----------------
extern "C" void kernel_launch(void* const* d_in, const int* in_sizes, int n_in,
                              void* d_out, int out_size) {
    const float* x_bus     = (const float*)d_in[0];
    const float* x_gen     = (const float*)d_in[1];
    const float* ea0       = (const float*)d_in[2];
    const float* ea1       = (const float*)d_in[3];
    const float* ea2       = (const float*)d_in[4];
    const float* W_lin_bus = (const float*)d_in[5];
    const float* b_lin_bus = (const float*)d_in[6];
    const float* W_lin_gen = (const float*)d_in[7];
    const float* b_lin_gen = (const float*)d_in[8];
    const float* W_elin    = (const float*)d_in[9];
    const float* b_elin    = (const float*)d_in[10];
    const float* Wn        = (const float*)d_in[11];
    const float* bn        = (const float*)d_in[12];
    const float* Et        = (const float*)d_in[13];
    const float* Wea       = (const float*)d_in[14];
    const float* Watt      = (const float*)d_in[15];
    const float* Wl        = (const float*)d_in[16];
    const float* bl        = (const float*)d_in[17];
    const float* W_out_bus = (const float*)d_in[18];
    const float* b_out_bus = (const float*)d_in[19];
    const float* W_out_gen = (const float*)d_in[20];
    const float* b_out_gen = (const float*)d_in[21];
    const int*   src       = (const int*)d_in[22];
    const int*   dst       = (const int*)d_in[23];
    float* out = (float*)d_out;

    float *x, *p, *a, *b, *s, *eae, *d, *Wc, *bc, *va, *vb, *cab, *c3;
    cudaGetSymbolAddress((void**)&x,   g_x);
    cudaGetSymbolAddress((void**)&p,   g_p);
    cudaGetSymbolAddress((void**)&a,   g_a);
    cudaGetSymbolAddress((void**)&b,   g_b);
    cudaGetSymbolAddress((void**)&s,   g_s);
    cudaGetSymbolAddress((void**)&eae, g_eae);
    cudaGetSymbolAddress((void**)&d,   g_d);
    cudaGetSymbolAddress((void**)&Wc,  g_Wc);
    cudaGetSymbolAddress((void**)&bc,  g_bc);
    cudaGetSymbolAddress((void**)&va,  g_va);
    cudaGetSymbolAddress((void**)&vb,  g_vb);
    cudaGetSymbolAddress((void**)&cab, g_cab);
    cudaGetSymbolAddress((void**)&c3,  g_c3);

    // one-time precompute
    prep_weights<<<6, 256>>>(Wn, bn, Wl, bl, Watt, Et);
    embed_nodes<16><<<(NBUS + 3) / 4, 256>>>(x_bus, W_lin_bus, b_lin_bus, x, NBUS);
    embed_nodes<8> <<<(NGEN + 3) / 4, 256>>>(x_gen, W_lin_gen, b_lin_gen, x + (size_t)NBUS * 64, NGEN);
    edge_pre<<<EE / EPB, 256>>>(ea0, ea1, ea2, W_elin, b_elin, Wea, Watt);

    for (int l = 0; l < LAY; l++) {
        int blk = l * 2;
        int use_s = (l > 0);
        gemm_node<<<(NBUS + 63) / 64, 256>>>(x, s, use_s, Wc + (size_t)blk * 4096,
                                             bc + blk * 64, va + blk * 64, vb + blk * 64,
                                             cab + blk * 2, p, a, b, NBUS);
        gemm_node<<<(NGEN + 63) / 64, 256>>>(x + (size_t)NBUS * 64, s + NBUS, use_s,
                                             Wc + (size_t)(blk + 1) * 4096, bc + (blk + 1) * 64,
                                             va + (blk + 1) * 64, vb + (blk + 1) * 64,
                                             cab + (blk + 1) * 2, p + (size_t)NBUS * 64,
                                             a + NBUS, b + NBUS, NGEN);
        zero_kernel<<<(NN * 16 + NN + 255) / 256, 256>>>((float4*)x, s);
        const float* Wl2 = Wl + (size_t)l * 80 * 64 + 64 * 64;
        edge_fused<<<EE / MEPB, 256>>>(a, b, d + (size_t)l * EE, c3 + l * 3, p,
                                       eae + (size_t)l * EE * 16, Wl2, src, dst, x, s);
    }

    out_kernel<<<((size_t)NN * 32 + 255) / 256, 256>>>(x, s, W_out_bus, b_out_bus,
                                                       W_out_gen, b_out_gen, out);
}

// round 5
// speedup vs baseline: 2.6338x; 1.0916x over previous
#include <cuda_runtime.h>

#define NBUS 200000
#define NGEN 50000
#define NN   (NBUS + NGEN)
#define EE0  500000
#define EE1  50000
#define EE2  50000
#define EE   (EE0 + EE1 + EE2)
#define LAY  3
#define NEG  0.2f

// ---------------- static device scratch ----------------
__device__ __align__(16) float g_Wc[6][4096];   // folded node weight [l*2+t][k][j]
__device__ float g_bc[6][64];                   // folded node bias
__device__ float g_va[6][64];                   // folded attention vec (dst)
__device__ float g_vb[6][64];                   // folded attention vec (src)
__device__ float g_cab[6][2];                   // folded attention scalars
__device__ float g_c3[9];                       // edge-type logit constants [l][etype]
__device__ __align__(16) float g_x[(size_t)NN * 64];   // unnormalized aggregate
__device__ __align__(16) float g_p[(size_t)NN * 64];
__device__ float g_a[NN];
__device__ float g_b[NN];
__device__ float g_s[NN];                       // softmax denominator (sum of exp)
__device__ __align__(16) float g_eae[(size_t)LAY * EE * 16];
__device__ float g_d[(size_t)LAY * EE];         // eae.w4 + c3[l][etype]  (c baked in)

__device__ __forceinline__ float lrelu(float v) { return v >= 0.f ? v : NEG * v; }

// ---------------- weight folding (once per call, 6 blocks) ----------------
__global__ void prep_weights(const float* __restrict__ Wn, const float* __restrict__ bn,
                             const float* __restrict__ Wl, const float* __restrict__ bl,
                             const float* __restrict__ Watt, const float* __restrict__ Et) {
    int blk = blockIdx.x;             // l*2 + t
    int l = blk >> 1, t = blk & 1;
    __shared__ float WnS[4096], Wl1S[4096];
    const float* wn   = Wn + (size_t)blk * 4096;
    const float* wl1  = Wl + (size_t)l * 80 * 64;
    const float* watt = Watt + l * 160;
    const float* bnl  = bn + blk * 64;
    int tid = threadIdx.x;
    for (int i = tid; i < 4096; i += 256) { WnS[i] = wn[i]; Wl1S[i] = wl1[i]; }
    __syncthreads();
    for (int idx = tid; idx < 4096; idx += 256) {
        int k = idx >> 6, j = idx & 63;
        float s = 0.f;
#pragma unroll 8
        for (int m = 0; m < 64; m++) s += WnS[k * 64 + m] * Wl1S[m * 64 + j];
        g_Wc[blk][idx] = s;
    }
    if (tid < 64) {
        int j = tid;
        float s = bl[l * 64 + j];
        for (int m = 0; m < 64; m++) s += bnl[m] * Wl1S[m * 64 + j];
        g_bc[blk][j] = s;
        float sa = 0.f, sb = 0.f;
        for (int m = 0; m < 64; m++) {
            sa += WnS[j * 64 + m] * watt[m];
            sb += WnS[j * 64 + m] * watt[64 + m];
        }
        g_va[blk][j] = sa; g_vb[blk][j] = sb;
    } else if (tid == 64) {
        float ca = 0.f, cb = 0.f;
        for (int m = 0; m < 64; m++) { ca += bnl[m] * watt[m]; cb += bnl[m] * watt[64 + m]; }
        g_cab[blk][0] = ca; g_cab[blk][1] = cb;
    } else if (tid >= 128 && tid < 131 && t == 0) {
        int tt = tid - 128;
        float s = 0.f;
        for (int j = 0; j < 16; j++) s += lrelu(Et[l * 48 + tt * 16 + j]) * watt[128 + j];
        g_c3[l * 3 + tt] = s;
    }
}

// ---------------- node input embed: out = relu(xin @ W + b) ----------------
template <int K>
__global__ void embed_nodes(const float* __restrict__ xin, const float* __restrict__ W,
                            const float* __restrict__ bias, float* __restrict__ xout, int rows) {
    __shared__ float Ws[K * 64];
    __shared__ float bs[64];
    __shared__ float xs[4 * K];
    int tid = threadIdx.x;
    for (int i = tid; i < K * 64; i += 256) Ws[i] = W[i];
    if (tid < 64) bs[tid] = bias[tid];
    int base = blockIdx.x * 4;
    for (int i = tid; i < 4 * K; i += 256) {
        int r = base + i / K;
        xs[i] = (r < rows) ? xin[(size_t)base * K + i] : 0.f;
    }
    __syncthreads();
    int j = tid & 63, s = tid >> 6;
    int n = base + s;
    if (n < rows) {
        float acc = bs[j];
#pragma unroll
        for (int k = 0; k < K; k++) acc += xs[s * K + k] * Ws[k * 64 + j];
        xout[(size_t)n * 64 + j] = fmaxf(acc, 0.f);
    }
}

// ---------------- edge precompute: eae[l], d[l]; grid-stride tiles, weights loaded once ----------------
#define EPB 64
#define NTILES (EE / EPB)   // 9375
__global__ void edge_pre(const float* __restrict__ ea0, const float* __restrict__ ea1,
                         const float* __restrict__ ea2, const float* __restrict__ W_elin,
                         const float* __restrict__ b_elin, const float* __restrict__ Wea,
                         const float* __restrict__ Watt) {
    __shared__ float We[1728];                  // [t][k][64]
    __shared__ float be[192];
    __shared__ __align__(16) float Wcat[4096];  // [k][64]: cols l*16+q (48 used)
    __shared__ float w4s[64];                   // [l][16] (+pad)
    __shared__ float c3s[12];
    __shared__ float raw[EPB * 9];
    __shared__ __align__(16) float eaT[64 * 68]; // [k][row]
    int tid = threadIdx.x;
    for (int i = tid; i < 1728; i += 256) We[i] = W_elin[i];
    if (tid < 192) be[tid] = b_elin[tid];
    for (int i = tid; i < 3072; i += 256) {      // Wea[l][m][16] -> Wcat[m][l*16+q]
        int l = i >> 10, rem = i & 1023, m = rem >> 4, q = rem & 15;
        Wcat[m * 64 + l * 16 + q] = Wea[i];
    }
    for (int i = tid; i < 1024; i += 256) {      // zero pad cols 48..63
        int m = i >> 4, q = i & 15;
        Wcat[m * 64 + 48 + q] = 0.f;
    }
    if (tid < 48) w4s[tid] = Watt[(tid >> 4) * 160 + 144 + (tid & 15)];
    else if (tid < 64) w4s[tid] = 0.f;
    if (tid >= 64 && tid < 73) c3s[tid - 64] = g_c3[tid - 64];

    for (int tile = blockIdx.x; tile < NTILES; tile += gridDim.x) {
        int base = tile * EPB;
        __syncthreads();   // protect raw/eaT reuse + first-iter weight load
        for (int i = tid; i < EPB * 9; i += 256) {
            int e = base + i / 9, k = i % 9;
            float v;
            if (e < EE0)            v = ea0[(size_t)e * 9 + k];
            else if (e < EE0 + EE1) v = ea1[(size_t)(e - EE0) * 9 + k];
            else                    v = ea2[(size_t)(e - EE0 - EE1) * 9 + k];
            raw[i] = v;
        }
        __syncthreads();
        // phase 1: ea64 = relu(raw @ W_elin[type] + b), stored transposed [k][row]
        for (int idx = tid; idx < EPB * 16; idx += 256) {
            int s = idx >> 4, cx = idx & 15;
            int e = base + s;
            int t = (e < EE0) ? 0 : ((e < EE0 + EE1) ? 1 : 2);
            float4 acc = ((const float4*)be)[t * 16 + cx];
#pragma unroll
            for (int k = 0; k < 9; k++) {
                float rv = raw[s * 9 + k];
                float4 wv = ((const float4*)We)[(t * 9 + k) * 16 + cx];
                acc.x += rv * wv.x; acc.y += rv * wv.y; acc.z += rv * wv.z; acc.w += rv * wv.w;
            }
            eaT[(4 * cx + 0) * 68 + s] = fmaxf(acc.x, 0.f);
            eaT[(4 * cx + 1) * 68 + s] = fmaxf(acc.y, 0.f);
            eaT[(4 * cx + 2) * 68 + s] = fmaxf(acc.z, 0.f);
            eaT[(4 * cx + 3) * 68 + s] = fmaxf(acc.w, 0.f);
        }
        __syncthreads();
        // phase 2: C[64 rows][64 cols] = eaT^T @ Wcat, 4x4 tile per thread
        int ty = tid >> 4, tx = tid & 15;
        float4 acc0 = make_float4(0.f,0.f,0.f,0.f), acc1 = acc0, acc2 = acc0, acc3 = acc0;
#pragma unroll 8
        for (int k = 0; k < 64; k++) {
            float4 av = *(const float4*)&eaT[k * 68 + 4 * ty];
            float4 wv = ((const float4*)Wcat)[k * 16 + tx];
            acc0.x += av.x * wv.x; acc0.y += av.x * wv.y; acc0.z += av.x * wv.z; acc0.w += av.x * wv.w;
            acc1.x += av.y * wv.x; acc1.y += av.y * wv.y; acc1.z += av.y * wv.z; acc1.w += av.y * wv.w;
            acc2.x += av.z * wv.x; acc2.y += av.z * wv.y; acc2.z += av.z * wv.z; acc2.w += av.z * wv.w;
            acc3.x += av.w * wv.x; acc3.y += av.w * wv.y; acc3.z += av.w * wv.z; acc3.w += av.w * wv.w;
        }
        acc0.x = lrelu(acc0.x); acc0.y = lrelu(acc0.y); acc0.z = lrelu(acc0.z); acc0.w = lrelu(acc0.w);
        acc1.x = lrelu(acc1.x); acc1.y = lrelu(acc1.y); acc1.z = lrelu(acc1.z); acc1.w = lrelu(acc1.w);
        acc2.x = lrelu(acc2.x); acc2.y = lrelu(acc2.y); acc2.z = lrelu(acc2.z); acc2.w = lrelu(acc2.w);
        acc3.x = lrelu(acc3.x); acc3.y = lrelu(acc3.y); acc3.z = lrelu(acc3.z); acc3.w = lrelu(acc3.w);
        int l = tx >> 2, q = tx & 3;
        int r0 = base + 4 * ty;
        if (tx < 12) {
            float4* eo = (float4*)g_eae;
            eo[((size_t)l * EE + r0 + 0) * 4 + q] = acc0;
            eo[((size_t)l * EE + r0 + 1) * 4 + q] = acc1;
            eo[((size_t)l * EE + r0 + 2) * 4 + q] = acc2;
            eo[((size_t)l * EE + r0 + 3) * 4 + q] = acc3;
        }
        float4 wv = ((const float4*)w4s)[((tx < 12) ? l : 0) * 4 + q];
        float d0 = acc0.x * wv.x + acc0.y * wv.y + acc0.z * wv.z + acc0.w * wv.w;
        float d1 = acc1.x * wv.x + acc1.y * wv.y + acc1.z * wv.z + acc1.w * wv.w;
        float d2 = acc2.x * wv.x + acc2.y * wv.y + acc2.z * wv.z + acc2.w * wv.w;
        float d3 = acc3.x * wv.x + acc3.y * wv.y + acc3.z * wv.z + acc3.w * wv.w;
#pragma unroll
        for (int off = 2; off; off >>= 1) {
            d0 += __shfl_down_sync(0xffffffffu, d0, off, 4);
            d1 += __shfl_down_sync(0xffffffffu, d1, off, 4);
            d2 += __shfl_down_sync(0xffffffffu, d2, off, 4);
            d3 += __shfl_down_sync(0xffffffffu, d3, off, 4);
        }
        if (q == 0 && tx < 12) {
            int e0 = r0;
#pragma unroll
            for (int i = 0; i < 4; i++) {
                int e = e0 + i;
                int t = (e < EE0) ? 0 : ((e < EE0 + EE1) ? 1 : 2);
                float dv = (i == 0) ? d0 : (i == 1) ? d1 : (i == 2) ? d2 : d3;
                g_d[(size_t)l * EE + e] = dv + c3s[l * 3 + t];
            }
        }
    }
}

// ---------------- fused node GEMM: p = relu(x/s)@Wc + bc, a/b scalars; grid-stride ----------------
__global__ void gemm_node(const float* __restrict__ x, const float* __restrict__ sden,
                          int use_s, const float* __restrict__ Wc,
                          const float* __restrict__ bc, const float* __restrict__ va,
                          const float* __restrict__ vb, const float* __restrict__ cab,
                          float* __restrict__ p, float* __restrict__ a, float* __restrict__ b,
                          int rows) {
    __shared__ float Ws[4096];            // [k][j]
    __shared__ float xsT[64 * 68];        // [k][row]
    __shared__ float vas[64], vbs[64], bcs[64], sdiv[64];
    int tid = threadIdx.x;
    for (int i = tid; i < 4096; i += 256) Ws[i] = Wc[i];
    if (tid < 64) { vas[tid] = va[tid]; vbs[tid] = vb[tid]; bcs[tid] = bc[tid]; }
    float ca = cab[0], cb = cab[1];
    int ntiles = (rows + 63) >> 6;
    for (int tile = blockIdx.x; tile < ntiles; tile += gridDim.x) {
        int base = tile * 64;
        int cnt = min(64, rows - base);
        __syncthreads();
        if (tid < 64) {
            float sv = 1.f;
            if (use_s && tid < cnt) sv = 1.f / (sden[base + tid] + 1e-16f);
            sdiv[tid] = sv;
        }
        __syncthreads();
        for (int idx = tid; idx < 4096; idx += 256) {
            int r = idx >> 6, k = idx & 63;
            float v = (r < cnt) ? fmaxf(x[(size_t)(base + r) * 64 + k], 0.f) * sdiv[r] : 0.f;
            xsT[k * 68 + r] = v;
        }
        __syncthreads();
        int ty = tid >> 4, tx = tid & 15;
        float4 acc0, acc1, acc2, acc3;
        {
            float4 bc4 = ((const float4*)bcs)[tx];
            acc0 = bc4; acc1 = bc4; acc2 = bc4; acc3 = bc4;
        }
#pragma unroll 8
        for (int k = 0; k < 64; k++) {
            float4 av = *(const float4*)&xsT[k * 68 + 4 * ty];
            float4 wv = ((const float4*)Ws)[k * 16 + tx];
            acc0.x += av.x * wv.x; acc0.y += av.x * wv.y; acc0.z += av.x * wv.z; acc0.w += av.x * wv.w;
            acc1.x += av.y * wv.x; acc1.y += av.y * wv.y; acc1.z += av.y * wv.z; acc1.w += av.y * wv.w;
            acc2.x += av.z * wv.x; acc2.y += av.z * wv.y; acc2.z += av.z * wv.z; acc2.w += av.z * wv.w;
            acc3.x += av.w * wv.x; acc3.y += av.w * wv.y; acc3.z += av.w * wv.z; acc3.w += av.w * wv.w;
        }
        float4* p4 = (float4*)p;
        int r0 = 4 * ty;
        if (r0 + 0 < cnt) p4[(size_t)(base + r0 + 0) * 16 + tx] = acc0;
        if (r0 + 1 < cnt) p4[(size_t)(base + r0 + 1) * 16 + tx] = acc1;
        if (r0 + 2 < cnt) p4[(size_t)(base + r0 + 2) * 16 + tx] = acc2;
        if (r0 + 3 < cnt) p4[(size_t)(base + r0 + 3) * 16 + tx] = acc3;
        int row = tid >> 2, q = tid & 3;
        float pa = 0.f, pb = 0.f;
#pragma unroll
        for (int kk = 0; kk < 16; kk++) {
            int k = q * 16 + kk;
            float v = xsT[k * 68 + row];
            pa += v * vas[k]; pb += v * vbs[k];
        }
#pragma unroll
        for (int off = 2; off; off >>= 1) {
            pa += __shfl_down_sync(0xffffffffu, pa, off, 4);
            pb += __shfl_down_sync(0xffffffffu, pb, off, 4);
        }
        if (q == 0 && row < cnt) {
            a[base + row] = pa + ca;
            b[base + row] = pb + cb;
        }
    }
}

// ---------------- zero accumulator + softmax denominator ----------------
__global__ void zero_kernel(float4* __restrict__ x4, float* __restrict__ s) {
    int i = blockIdx.x * 256 + threadIdx.x;
    if (i < NN * 16) { x4[i] = make_float4(0.f, 0.f, 0.f, 0.f); return; }
    int r = i - NN * 16;
    if (r < NN) s[r] = 0.f;
}

// ---------------- fused edge pass: logit + exp + unnormalized message scatter ----------------
#define MEPB 128
__global__ void edge_fused(const float* __restrict__ a, const float* __restrict__ b,
                           const float* __restrict__ d,
                           const float* __restrict__ p, const float* __restrict__ eae,
                           const float* __restrict__ Wl2, const int* __restrict__ src,
                           const int* __restrict__ dst, float* __restrict__ x,
                           float* __restrict__ s) {
    __shared__ float Wl2S[1024];          // [k][j] 16x64
    int tid = threadIdx.x;
    for (int i = tid; i < 1024; i += 256) Wl2S[i] = Wl2[i];
    __syncthreads();
    int sg = tid >> 4, t = tid & 15;
    int base0 = blockIdx.x * MEPB;
#pragma unroll
    for (int pass = 0; pass < MEPB / 16; pass++) {
        int e = base0 + pass * 16 + sg;
        if (e >= EE) break;
        int de = dst[e], se = src[e];
        float myea = eae[(size_t)e * 16 + t];
        float lg = lrelu(a[de] + b[se] + d[e]);
        float ex = __expf(lg);
        float4 acc = ((const float4*)p)[(size_t)se * 16 + t];
#pragma unroll
        for (int k = 0; k < 16; k++) {
            float evv = __shfl_sync(0xffffffffu, myea, k, 16);
            float4 wv = ((const float4*)Wl2S)[k * 16 + t];
            acc.x += evv * wv.x; acc.y += evv * wv.y; acc.z += evv * wv.z; acc.w += evv * wv.w;
        }
        acc.x *= ex; acc.y *= ex; acc.z *= ex; acc.w *= ex;
        float* addr = x + (size_t)de * 64 + 4 * t;
        asm volatile("red.global.add.v4.f32 [%0], {%1, %2, %3, %4};"
                     :: "l"(addr), "f"(acc.x), "f"(acc.y), "f"(acc.z), "f"(acc.w)
                     : "memory");
        if (t == 0) atomicAdd(&s[de], ex);
    }
}

// ---------------- output: sigmoid((relu(x)/s) @ W_out + b) ----------------
__global__ void out_kernel(const float* __restrict__ x, const float* __restrict__ sden,
                           const float* __restrict__ Wb, const float* __restrict__ bb,
                           const float* __restrict__ Wg, const float* __restrict__ bg,
                           float* __restrict__ out) {
    int gt = blockIdx.x * 256 + threadIdx.x;
    int n = gt >> 5, lane = gt & 31;
    if (n >= NN) return;
    float sinv = 1.f / (sden[n] + 1e-16f);
    float v0 = fmaxf(x[(size_t)n * 64 + lane], 0.f) * sinv;
    float v1 = fmaxf(x[(size_t)n * 64 + 32 + lane], 0.f) * sinv;
    const float* W = (n < NBUS) ? Wb : Wg;
    float a0 = v0 * __ldg(&W[lane * 2])     + v1 * __ldg(&W[(lane + 32) * 2]);
    float a1 = v0 * __ldg(&W[lane * 2 + 1]) + v1 * __ldg(&W[(lane + 32) * 2 + 1]);
#pragma unroll
    for (int off = 16; off; off >>= 1) {
        a0 += __shfl_down_sync(0xffffffffu, a0, off);
        a1 += __shfl_down_sync(0xffffffffu, a1, off);
    }
    if (lane == 0) {
        const float* bias = (n < NBUS) ? bb : bg;
        float z0 = a0 + bias[0], z1 = a1 + bias[1];
        out[(size_t)n * 2 + 0] = 1.f / (1.f + __expf(-z0));
        out[(size_t)n * 2 + 1] = 1.f / (1.f + __expf(-z1));
    }
}

// ---------------- host launcher ----------------
extern "C" void kernel_launch(void* const* d_in, const int* in_sizes, int n_in,
                              void* d_out, int out_size) {
    const float* x_bus     = (const float*)d_in[0];
    const float* x_gen     = (const float*)d_in[1];
    const float* ea0       = (const float*)d_in[2];
    const float* ea1       = (const float*)d_in[3];
    const float* ea2       = (const float*)d_in[4];
    const float* W_lin_bus = (const float*)d_in[5];
    const float* b_lin_bus = (const float*)d_in[6];
    const float* W_lin_gen = (const float*)d_in[7];
    const float* b_lin_gen = (const float*)d_in[8];
    const float* W_elin    = (const float*)d_in[9];
    const float* b_elin    = (const float*)d_in[10];
    const float* Wn        = (const float*)d_in[11];
    const float* bn        = (const float*)d_in[12];
    const float* Et        = (const float*)d_in[13];
    const float* Wea       = (const float*)d_in[14];
    const float* Watt      = (const float*)d_in[15];
    const float* Wl        = (const float*)d_in[16];
    const float* bl        = (const float*)d_in[17];
    const float* W_out_bus = (const float*)d_in[18];
    const float* b_out_bus = (const float*)d_in[19];
    const float* W_out_gen = (const float*)d_in[20];
    const float* b_out_gen = (const float*)d_in[21];
    const int*   src       = (const int*)d_in[22];
    const int*   dst       = (const int*)d_in[23];
    float* out = (float*)d_out;

    float *x, *p, *a, *b, *s, *eae, *d, *Wc, *bc, *va, *vb, *cab;
    cudaGetSymbolAddress((void**)&x,   g_x);
    cudaGetSymbolAddress((void**)&p,   g_p);
    cudaGetSymbolAddress((void**)&a,   g_a);
    cudaGetSymbolAddress((void**)&b,   g_b);
    cudaGetSymbolAddress((void**)&s,   g_s);
    cudaGetSymbolAddress((void**)&eae, g_eae);
    cudaGetSymbolAddress((void**)&d,   g_d);
    cudaGetSymbolAddress((void**)&Wc,  g_Wc);
    cudaGetSymbolAddress((void**)&bc,  g_bc);
    cudaGetSymbolAddress((void**)&va,  g_va);
    cudaGetSymbolAddress((void**)&vb,  g_vb);
    cudaGetSymbolAddress((void**)&cab, g_cab);

    // one-time precompute
    prep_weights<<<6, 256>>>(Wn, bn, Wl, bl, Watt, Et);
    embed_nodes<16><<<(NBUS + 3) / 4, 256>>>(x_bus, W_lin_bus, b_lin_bus, x, NBUS);
    embed_nodes<8> <<<(NGEN + 3) / 4, 256>>>(x_gen, W_lin_gen, b_lin_gen, x + (size_t)NBUS * 64, NGEN);
    edge_pre<<<(NTILES + 3) / 4, 256>>>(ea0, ea1, ea2, W_elin, b_elin, Wea, Watt);

    for (int l = 0; l < LAY; l++) {
        int blk = l * 2;
        int use_s = (l > 0);
        int tb = (NBUS / 64 + 1) / 2;           // 2 tiles per block
        int tg = ((NGEN + 63) / 64 + 1) / 2;
        gemm_node<<<tb, 256>>>(x, s, use_s, Wc + (size_t)blk * 4096,
                               bc + blk * 64, va + blk * 64, vb + blk * 64,
                               cab + blk * 2, p, a, b, NBUS);
        gemm_node<<<tg, 256>>>(x + (size_t)NBUS * 64, s + NBUS, use_s,
                               Wc + (size_t)(blk + 1) * 4096, bc + (blk + 1) * 64,
                               va + (blk + 1) * 64, vb + (blk + 1) * 64,
                               cab + (blk + 1) * 2, p + (size_t)NBUS * 64,
                               a + NBUS, b + NBUS, NGEN);
        zero_kernel<<<(NN * 16 + NN + 255) / 256, 256>>>((float4*)x, s);
        const float* Wl2 = Wl + (size_t)l * 80 * 64 + 64 * 64;
        edge_fused<<<(EE + MEPB - 1) / MEPB, 256>>>(a, b, d + (size_t)l * EE, p,
                                                    eae + (size_t)l * EE * 16, Wl2,
                                                    src, dst, x, s);
    }

    out_kernel<<<((size_t)NN * 32 + 255) / 256, 256>>>(x, s, W_out_bus, b_out_bus,
                                                       W_out_gen, b_out_gen, out);
}